// round 8
// baseline (speedup 1.0000x reference)
#include <cuda_runtime.h>
#include <cuda_fp16.h>
#include <cstdint>

// Problem constants
#define BB   16
#define SS   577
#define DD   1408
#define HH   16
#define HD   88
#define SCALE_F 0.10660035817780521f  // 1/sqrt(88)

#define MM   (BB * SS)      // 9232
#define N1   (3 * DD)       // 4224
#define KK   DD             // 1408

// ---------------------------------------------------------------------------
// Device-global scratch (fp16 hi/lo split everywhere)
// ---------------------------------------------------------------------------
__device__ __half g_hsH[(size_t)MM * KK];
__device__ __half g_hsL[(size_t)MM * KK];
__device__ __half g_qkvH[(size_t)MM * N1];
__device__ __half g_qkvL[(size_t)MM * N1];
__device__ __half g_attH[(size_t)MM * KK];
__device__ __half g_attL[(size_t)MM * KK];
__device__ __half g_wqkvH[(size_t)N1 * KK];   // transposed [N,K]
__device__ __half g_wqkvL[(size_t)N1 * KK];
__device__ __half g_wprojH[(size_t)DD * KK];  // transposed [N,K]
__device__ __half g_wprojL[(size_t)DD * KK];

// ---------------------------------------------------------------------------
// PTX helpers (sm_80+ only; harness targets sm_103 w/o 'a' — no tcgen05)
// ---------------------------------------------------------------------------
__device__ __forceinline__ uint32_t smem_to_u32(const void* p) {
    uint32_t a;
    asm("{ .reg .u64 t; cvta.to.shared.u64 t, %1; cvt.u32.u64 %0, t; }"
        : "=r"(a) : "l"(p));
    return a;
}
__device__ __forceinline__ void cp16(uint32_t dst, const void* src, uint32_t sz) {
    asm volatile("cp.async.ca.shared.global [%0], [%1], 16, %2;"
                 :: "r"(dst), "l"(src), "r"(sz) : "memory");
}
#define CP_COMMIT() asm volatile("cp.async.commit_group;" ::: "memory")
#define CP_WAIT(n)  asm volatile("cp.async.wait_group %0;" :: "n"(n) : "memory")

__device__ __forceinline__ void ldsm_x4(uint32_t* r, uint32_t addr) {
    asm volatile("ldmatrix.sync.aligned.m8n8.x4.shared.b16 {%0,%1,%2,%3}, [%4];"
                 : "=r"(r[0]), "=r"(r[1]), "=r"(r[2]), "=r"(r[3]) : "r"(addr));
}
__device__ __forceinline__ void ldsm_x2(uint32_t* r, uint32_t addr) {
    asm volatile("ldmatrix.sync.aligned.m8n8.x2.shared.b16 {%0,%1}, [%2];"
                 : "=r"(r[0]), "=r"(r[1]) : "r"(addr));
}
__device__ __forceinline__ void ldsm_x2t(uint32_t* r, uint32_t addr) {
    asm volatile("ldmatrix.sync.aligned.m8n8.x2.trans.shared.b16 {%0,%1}, [%2];"
                 : "=r"(r[0]), "=r"(r[1]) : "r"(addr));
}
// fp16 inputs, fp32 accumulate (main term)
__device__ __forceinline__ void mma_f32(float* d, const uint32_t* a, const uint32_t* b) {
    asm volatile("mma.sync.aligned.m16n8k16.row.col.f32.f16.f16.f32 "
                 "{%0,%1,%2,%3}, {%4,%5,%6,%7}, {%8,%9}, {%0,%1,%2,%3};"
                 : "+f"(d[0]), "+f"(d[1]), "+f"(d[2]), "+f"(d[3])
                 : "r"(a[0]), "r"(a[1]), "r"(a[2]), "r"(a[3]), "r"(b[0]), "r"(b[1]));
}
// fp16 inputs, fp16 accumulate (small cross terms)
__device__ __forceinline__ void mma_f16(uint32_t* d, const uint32_t* a, const uint32_t* b) {
    asm volatile("mma.sync.aligned.m16n8k16.row.col.f16.f16.f16.f16 "
                 "{%0,%1}, {%2,%3,%4,%5}, {%6,%7}, {%0,%1};"
                 : "+r"(d[0]), "+r"(d[1])
                 : "r"(a[0]), "r"(a[1]), "r"(a[2]), "r"(a[3]), "r"(b[0]), "r"(b[1]));
}
__device__ __forceinline__ void split_pair(float a, float b, uint32_t& hi, uint32_t& lo) {
    __half ha = __float2half_rn(a), hb = __float2half_rn(b);
    float la = a - __half2float(ha), lb = b - __half2float(hb);
    __half hla = __float2half_rn(la), hlb = __float2half_rn(lb);
    hi = ((uint32_t)__half_as_ushort(hb) << 16) | __half_as_ushort(ha);
    lo = ((uint32_t)__half_as_ushort(hlb) << 16) | __half_as_ushort(hla);
}
// unpack fp16x2 accumulator reg and add into two fp32 accumulators
__device__ __forceinline__ void drain_h2(uint32_t h2, float& d0, float& d1) {
    __half2 h = *reinterpret_cast<__half2*>(&h2);
    float2 f = __half22float2(h);
    d0 += f.x;
    d1 += f.y;
}

// ---------------------------------------------------------------------------
// Split fp32 -> (hi, lo) fp16, same layout.
// ---------------------------------------------------------------------------
__global__ void split_kernel(const float4* __restrict__ in,
                             uint2* __restrict__ hi, uint2* __restrict__ lo, int n4)
{
    int i = blockIdx.x * blockDim.x + threadIdx.x;
    if (i >= n4) return;
    float4 v = in[i];
    uint2 ho, loo;
    split_pair(v.x, v.y, ho.x, loo.x);
    split_pair(v.z, v.w, ho.y, loo.y);
    hi[i] = ho;
    lo[i] = loo;
}

// ---------------------------------------------------------------------------
// Transpose + split: in fp32 [R, C] -> hi/lo fp16 [C, R]
// ---------------------------------------------------------------------------
__global__ void tsplit_kernel(const float* __restrict__ in,
                              __half* __restrict__ hi,
                              __half* __restrict__ lo, int R, int C)
{
    __shared__ float t[32][33];
    int c0 = blockIdx.x * 32, r0 = blockIdx.y * 32;
    int tx = threadIdx.x, ty = threadIdx.y;
#pragma unroll
    for (int i = ty; i < 32; i += 8)
        t[i][tx] = in[(size_t)(r0 + i) * C + c0 + tx];
    __syncthreads();
#pragma unroll
    for (int i = ty; i < 32; i += 8) {
        float x = t[tx][i];
        __half h = __float2half_rn(x);
        __half l = __float2half_rn(x - __half2float(h));
        size_t off = (size_t)(c0 + i) * R + r0 + tx;
        hi[off] = h;
        lo[off] = l;
    }
}

// ---------------------------------------------------------------------------
// fp16-split MMA GEMM: C[M,N] = A[M,K] @ B[N,K]^T + bias[N]
// main term AhBh in fp32-accum; cross terms AhBl + AlBh in fp16-accum
// (cross magnitude ~3e-4 of C; fp16 accumulation error ~1e-6 rel).
// CTA 128x128, BK=32, 3 stages, 8 warps (4M x 2N), warp tile 32x64.
// MODE 0: fp32 C out.  MODE 1: fp16 hi/lo out, cols<DD scaled by SCALE_F.
// ---------------------------------------------------------------------------
#define BK      32
#define STAGES  3
#define TBYTES  8192
#define STAGE_BYTES (4 * TBYTES)
#define NCH     (KK / BK)

__device__ __forceinline__ uint32_t swz(int r, int c) {
    return (uint32_t)(r * 64 + ((c ^ ((r >> 1) & 3)) << 4));
}

template<int MODE>
__global__ __launch_bounds__(256, 1) void gemm_mma_kernel(
    const __half* __restrict__ Ahi, const __half* __restrict__ Alo,
    const __half* __restrict__ Bhi, const __half* __restrict__ Blo,
    const float* __restrict__ bias, float* __restrict__ C,
    __half* __restrict__ CH, __half* __restrict__ CL,
    int M, int N)
{
    extern __shared__ char smem[];
    const uint32_t sbase = smem_to_u32(smem);

    const int tid = threadIdx.x;
    const int lane = tid & 31;
    const int wid = tid >> 5;
    const int wm = wid & 3;
    const int wn = wid >> 2;
    const int m0 = blockIdx.y * 128;
    const int n0 = blockIdx.x * 128;

    auto load_stage = [&](int kt, int slot) {
        const int k0 = kt * BK;
        const uint32_t st = sbase + slot * STAGE_BYTES;
#pragma unroll
        for (int i = 0; i < 8; ++i) {
            int idx = tid + i * 256;
            int tile = idx >> 9;
            int rem = idx & 511;
            int r = rem >> 2;
            int c = rem & 3;
            uint32_t dst = st + tile * TBYTES + swz(r, c);
            const __half* gp;
            uint32_t sz = 16;
            if (tile < 2) {
                int m = m0 + r;
                int mc = m < M ? m : 0;
                if (m >= M) sz = 0;
                gp = (tile == 0 ? Ahi : Alo) + (size_t)mc * KK + k0 + c * 8;
            } else {
                int n = n0 + r;
                gp = (tile == 2 ? Bhi : Blo) + (size_t)n * KK + k0 + c * 8;
            }
            cp16(dst, gp, sz);
        }
        CP_COMMIT();
    };

    float acc[2][8][4];
    uint2 accx[2][8];
#pragma unroll
    for (int t = 0; t < 2; ++t)
#pragma unroll
        for (int j = 0; j < 8; ++j) {
#pragma unroll
            for (int v = 0; v < 4; ++v) acc[t][j][v] = 0.f;
            accx[t][j].x = 0u;
            accx[t][j].y = 0u;
        }

    load_stage(0, 0);
    load_stage(1, 1);

    const int ar[2] = { wm * 32 + (lane & 15), wm * 32 + 16 + (lane & 15) };
    const int acl = (lane >> 4);
    const int br = wn * 64 + (lane & 7) + ((lane >> 4) & 1) * 8;
    const int bcl = (lane >> 3) & 1;

    for (int kt = 0; kt < NCH; ++kt) {
        CP_WAIT(1);
        __syncthreads();
        if (kt + 2 < NCH) load_stage(kt + 2, (kt + 2) % STAGES);

        const uint32_t st = sbase + (kt % STAGES) * STAGE_BYTES;
#pragma unroll
        for (int ks = 0; ks < 2; ++ks) {
            uint32_t ah[2][4], al[2][4], bh[4][4], bl[4][4];
#pragma unroll
            for (int t = 0; t < 2; ++t)
                ldsm_x4(ah[t], st + 0 * TBYTES + swz(ar[t], ks * 2 + acl));
#pragma unroll
            for (int jj = 0; jj < 4; ++jj)
                ldsm_x4(bh[jj], st + 2 * TBYTES + swz(br + jj * 16, ks * 2 + bcl));
            // main term: fp32 accumulate
#pragma unroll
            for (int t = 0; t < 2; ++t)
#pragma unroll
                for (int jj = 0; jj < 4; ++jj) {
                    mma_f32(acc[t][jj * 2 + 0], ah[t], &bh[jj][0]);
                    mma_f32(acc[t][jj * 2 + 1], ah[t], &bh[jj][2]);
                }
            // cross terms: fp16 accumulate
#pragma unroll
            for (int jj = 0; jj < 4; ++jj)
                ldsm_x4(bl[jj], st + 3 * TBYTES + swz(br + jj * 16, ks * 2 + bcl));
#pragma unroll
            for (int t = 0; t < 2; ++t)
                ldsm_x4(al[t], st + 1 * TBYTES + swz(ar[t], ks * 2 + acl));
#pragma unroll
            for (int t = 0; t < 2; ++t)
#pragma unroll
                for (int jj = 0; jj < 4; ++jj) {
                    mma_f16(&accx[t][jj * 2 + 0].x, ah[t], &bl[jj][0]);
                    mma_f16(&accx[t][jj * 2 + 1].x, ah[t], &bl[jj][2]);
                }
#pragma unroll
            for (int t = 0; t < 2; ++t)
#pragma unroll
                for (int jj = 0; jj < 4; ++jj) {
                    mma_f16(&accx[t][jj * 2 + 0].x, al[t], &bh[jj][0]);
                    mma_f16(&accx[t][jj * 2 + 1].x, al[t], &bh[jj][2]);
                }
        }
    }

    // drain fp16 cross accumulators into fp32
#pragma unroll
    for (int t = 0; t < 2; ++t)
#pragma unroll
        for (int j = 0; j < 8; ++j) {
            drain_h2(accx[t][j].x, acc[t][j][0], acc[t][j][1]);
            drain_h2(accx[t][j].y, acc[t][j][2], acc[t][j][3]);
        }

    const int rb = m0 + wm * 32 + (lane >> 2);
    const int cb = n0 + wn * 64 + (lane & 3) * 2;
#pragma unroll
    for (int t = 0; t < 2; ++t) {
        int r0 = rb + t * 16;
#pragma unroll
        for (int j = 0; j < 8; ++j) {
            int col = cb + j * 8;
            float2 b2 = *(const float2*)&bias[col];
            if constexpr (MODE == 0) {
                if (r0 < M) {
                    float2 o = {acc[t][j][0] + b2.x, acc[t][j][1] + b2.y};
                    *(float2*)&C[(size_t)r0 * N + col] = o;
                }
                if (r0 + 8 < M) {
                    float2 o = {acc[t][j][2] + b2.x, acc[t][j][3] + b2.y};
                    *(float2*)&C[(size_t)(r0 + 8) * N + col] = o;
                }
            } else {
                float s = (col < DD) ? SCALE_F : 1.0f;
                if (r0 < M) {
                    uint32_t hi, lo;
                    split_pair((acc[t][j][0] + b2.x) * s, (acc[t][j][1] + b2.y) * s, hi, lo);
                    *(uint32_t*)&CH[(size_t)r0 * N + col] = hi;
                    *(uint32_t*)&CL[(size_t)r0 * N + col] = lo;
                }
                if (r0 + 8 < M) {
                    uint32_t hi, lo;
                    split_pair((acc[t][j][2] + b2.x) * s, (acc[t][j][3] + b2.y) * s, hi, lo);
                    *(uint32_t*)&CH[(size_t)(r0 + 8) * N + col] = hi;
                    *(uint32_t*)&CL[(size_t)(r0 + 8) * N + col] = lo;
                }
            }
        }
    }
}

// ---------------------------------------------------------------------------
// Tensor-core flash attention, fp16 split, cross terms in fp16-accum
// (drained to fp32 every kt).
// ---------------------------------------------------------------------------
#define SM_QH   0
#define SM_QL   24576
#define SM_KV   49152
#define SM_PH   147456
#define SM_PL   163840
#define SM_STAT 180224
#define SM_ATT_TOTAL 182272

__device__ __forceinline__ uint32_t swzQ(int r, int c) {
    return (uint32_t)(r * 192 + ((c ^ ((r >> 1) & 3)) << 4));
}
__device__ __forceinline__ uint32_t swzP(int r, int c) {
    return (uint32_t)(r * 128 + ((c ^ (r & 7)) << 4));
}

__global__ __launch_bounds__(256, 1) void attn_tc_kernel(
    const __half* __restrict__ qkvH, const __half* __restrict__ qkvL,
    __half* __restrict__ attH, __half* __restrict__ attL)
{
    extern __shared__ char smem[];
    const uint32_t sb = smem_to_u32(smem);
    const int tid = threadIdx.x;
    const int lane = tid & 31;
    const int wid = tid >> 5;
    const int wm = wid & 3;
    const int wn = wid >> 2;
    const int b = blockIdx.z;
    const int h = blockIdx.y;
    const int q0 = blockIdx.x * 128;

    float* sMax = (float*)(smem + SM_STAT);
    float* sSum = (float*)(smem + SM_STAT + 1024);

    const size_t rowbase = (size_t)b * SS * N1 + (size_t)h * HD;

    {
        int r = tid >> 1;
        int cbase = (tid & 1) * 6;
        int s = q0 + r;
        int sc_ = s < SS ? s : SS - 1;
        const __half* srcH = qkvH + rowbase + (size_t)sc_ * N1;
        const __half* srcL = qkvL + rowbase + (size_t)sc_ * N1;
#pragma unroll
        for (int cc = 0; cc < 6; ++cc) {
            int c = cbase + cc;
            int ca = c < 11 ? c : 10;
            uint32_t sz = (c < 11 && s < SS) ? 16 : 0;
            cp16(sb + SM_QH + swzQ(r, c), srcH + ca * 8, sz);
            cp16(sb + SM_QL + swzQ(r, c), srcL + ca * 8, sz);
        }
    }

    auto load_kv = [&](int kt, int buf) {
        int r = tid >> 2;
        int cbase = (tid & 3) * 3;
        int s = kt * 64 + r;
        int sc_ = s < SS ? s : SS - 1;
        const uint32_t kb = sb + SM_KV + buf * 49152;
        const __half* base[4] = {
            qkvH + rowbase + (size_t)sc_ * N1 + DD,
            qkvL + rowbase + (size_t)sc_ * N1 + DD,
            qkvH + rowbase + (size_t)sc_ * N1 + 2 * DD,
            qkvL + rowbase + (size_t)sc_ * N1 + 2 * DD
        };
#pragma unroll
        for (int arr = 0; arr < 4; ++arr) {
#pragma unroll
            for (int cc = 0; cc < 3; ++cc) {
                int c = cbase + cc;
                int ca = c < 11 ? c : 10;
                uint32_t sz = (c < 11 && s < SS) ? 16 : 0;
                cp16(kb + arr * 12288 + swzQ(r, c), base[arr] + ca * 8, sz);
            }
        }
    };

    load_kv(0, 0);
    CP_COMMIT();

    float acc[2][6][4];
#pragma unroll
    for (int ti = 0; ti < 2; ++ti)
#pragma unroll
        for (int j = 0; j < 6; ++j)
#pragma unroll
            for (int v = 0; v < 4; ++v) acc[ti][j][v] = 0.f;
    float m_old[2][2] = {{-1e30f, -1e30f}, {-1e30f, -1e30f}};
    float l_run[2][2] = {{0.f, 0.f}, {0.f, 0.f}};

    const int NKT = (SS + 63) / 64;

    for (int kt = 0; kt < NKT; ++kt) {
        CP_WAIT(0);
        __syncthreads();
        if (kt + 1 < NKT) load_kv(kt + 1, (kt + 1) & 1);
        CP_COMMIT();

        const uint32_t kb = sb + SM_KV + (kt & 1) * 49152;

        // ---- QK^T ----
        float sc[2][4][4];
        uint2 scx[2][4];
#pragma unroll
        for (int ti = 0; ti < 2; ++ti)
#pragma unroll
            for (int j = 0; j < 4; ++j) {
#pragma unroll
                for (int v = 0; v < 4; ++v) sc[ti][j][v] = 0.f;
                scx[ti][j].x = 0u;
                scx[ti][j].y = 0u;
            }

#pragma unroll
        for (int ks = 0; ks < 6; ++ks) {
            uint32_t ah[2][4], al[2][4], bh[4][2], bl[4][2];
#pragma unroll
            for (int ti = 0; ti < 2; ++ti) {
                int r = wm * 32 + ti * 16 + (lane & 15);
                int c = ks * 2 + (lane >> 4);
                uint32_t off = swzQ(r, c);
                ldsm_x4(ah[ti], sb + SM_QH + off);
                ldsm_x4(al[ti], sb + SM_QL + off);
            }
#pragma unroll
            for (int j = 0; j < 4; ++j) {
                int r = wn * 32 + j * 8 + (lane & 7);
                int c = ks * 2 + ((lane >> 3) & 1);
                uint32_t off = swzQ(r, c);
                ldsm_x2(bh[j], kb + 0 + off);
                ldsm_x2(bl[j], kb + 12288 + off);
            }
#pragma unroll
            for (int ti = 0; ti < 2; ++ti)
#pragma unroll
                for (int j = 0; j < 4; ++j)
                    mma_f32(sc[ti][j], ah[ti], bh[j]);
#pragma unroll
            for (int ti = 0; ti < 2; ++ti)
#pragma unroll
                for (int j = 0; j < 4; ++j)
                    mma_f16(&scx[ti][j].x, ah[ti], bl[j]);
#pragma unroll
            for (int ti = 0; ti < 2; ++ti)
#pragma unroll
                for (int j = 0; j < 4; ++j)
                    mma_f16(&scx[ti][j].x, al[ti], bh[j]);
        }
        // drain cross into fp32 scores
#pragma unroll
        for (int ti = 0; ti < 2; ++ti)
#pragma unroll
            for (int j = 0; j < 4; ++j) {
                drain_h2(scx[ti][j].x, sc[ti][j][0], sc[ti][j][1]);
                drain_h2(scx[ti][j].y, sc[ti][j][2], sc[ti][j][3]);
            }

        // ---- mask ----
#pragma unroll
        for (int j = 0; j < 4; ++j) {
            int c0 = kt * 64 + wn * 32 + j * 8 + (lane & 3) * 2;
            if (c0 >= SS) { sc[0][j][0] = sc[0][j][2] = sc[1][j][0] = sc[1][j][2] = -1e30f; }
            if (c0 + 1 >= SS) { sc[0][j][1] = sc[0][j][3] = sc[1][j][1] = sc[1][j][3] = -1e30f; }
        }

        // ---- row max ----
#pragma unroll
        for (int ti = 0; ti < 2; ++ti)
#pragma unroll
            for (int hh = 0; hh < 2; ++hh) {
                float mt = -1e30f;
#pragma unroll
                for (int j = 0; j < 4; ++j)
                    mt = fmaxf(mt, fmaxf(sc[ti][j][hh * 2], sc[ti][j][hh * 2 + 1]));
                mt = fmaxf(mt, __shfl_xor_sync(0xffffffffu, mt, 1));
                mt = fmaxf(mt, __shfl_xor_sync(0xffffffffu, mt, 2));
                if ((lane & 3) == 0) {
                    int rl = wm * 32 + ti * 16 + hh * 8 + (lane >> 2);
                    sMax[wn * 128 + rl] = mt;
                }
            }
        __syncthreads();

        float mnew[2][2], corr[2][2];
#pragma unroll
        for (int ti = 0; ti < 2; ++ti)
#pragma unroll
            for (int hh = 0; hh < 2; ++hh) {
                int rl = wm * 32 + ti * 16 + hh * 8 + (lane >> 2);
                float m2 = fmaxf(sMax[rl], sMax[128 + rl]);
                float mn = fmaxf(m_old[ti][hh], m2);
                corr[ti][hh] = __expf(m_old[ti][hh] - mn);
                mnew[ti][hh] = mn;
                m_old[ti][hh] = mn;
            }

        // ---- exp, P store (fp16 hi/lo), sums ----
        float sum_[2][2] = {{0.f, 0.f}, {0.f, 0.f}};
#pragma unroll
        for (int ti = 0; ti < 2; ++ti) {
            int r0 = wm * 32 + ti * 16 + (lane >> 2);
#pragma unroll
            for (int j = 0; j < 4; ++j) {
                float p0 = __expf(sc[ti][j][0] - mnew[ti][0]);
                float p1 = __expf(sc[ti][j][1] - mnew[ti][0]);
                float p2 = __expf(sc[ti][j][2] - mnew[ti][1]);
                float p3 = __expf(sc[ti][j][3] - mnew[ti][1]);
                sum_[ti][0] += p0 + p1;
                sum_[ti][1] += p2 + p3;
                int colc = wn * 32 + j * 8 + (lane & 3) * 2;
                uint32_t o0 = swzP(r0, colc >> 3) + (colc & 7) * 2;
                uint32_t o1 = swzP(r0 + 8, colc >> 3) + (colc & 7) * 2;
                uint32_t hi, lo;
                split_pair(p0, p1, hi, lo);
                *(uint32_t*)(smem + SM_PH + o0) = hi;
                *(uint32_t*)(smem + SM_PL + o0) = lo;
                split_pair(p2, p3, hi, lo);
                *(uint32_t*)(smem + SM_PH + o1) = hi;
                *(uint32_t*)(smem + SM_PL + o1) = lo;
            }
        }
#pragma unroll
        for (int ti = 0; ti < 2; ++ti)
#pragma unroll
            for (int hh = 0; hh < 2; ++hh) {
                float s = sum_[ti][hh];
                s += __shfl_xor_sync(0xffffffffu, s, 1);
                s += __shfl_xor_sync(0xffffffffu, s, 2);
                if ((lane & 3) == 0) {
                    int rl = wm * 32 + ti * 16 + hh * 8 + (lane >> 2);
                    sSum[wn * 128 + rl] = s;
                }
            }
#pragma unroll
        for (int ti = 0; ti < 2; ++ti)
#pragma unroll
            for (int j = 0; j < 6; ++j) {
                acc[ti][j][0] *= corr[ti][0];
                acc[ti][j][1] *= corr[ti][0];
                acc[ti][j][2] *= corr[ti][1];
                acc[ti][j][3] *= corr[ti][1];
            }
        __syncthreads();
#pragma unroll
        for (int ti = 0; ti < 2; ++ti)
#pragma unroll
            for (int hh = 0; hh < 2; ++hh) {
                int rl = wm * 32 + ti * 16 + hh * 8 + (lane >> 2);
                l_run[ti][hh] = l_run[ti][hh] * corr[ti][hh] + sSum[rl] + sSum[128 + rl];
            }

        // ---- P.V ----
        uint2 accx[2][6];
#pragma unroll
        for (int ti = 0; ti < 2; ++ti)
#pragma unroll
            for (int j = 0; j < 6; ++j) { accx[ti][j].x = 0u; accx[ti][j].y = 0u; }

#pragma unroll
        for (int ks = 0; ks < 4; ++ks) {
            uint32_t ph[2][4], pl[2][4], vh[6][2], vl[6][2];
#pragma unroll
            for (int ti = 0; ti < 2; ++ti) {
                int r = wm * 32 + ti * 16 + (lane & 15);
                int c = ks * 2 + (lane >> 4);
                uint32_t off = swzP(r, c);
                ldsm_x4(ph[ti], sb + SM_PH + off);
                ldsm_x4(pl[ti], sb + SM_PL + off);
            }
#pragma unroll
            for (int j = 0; j < 6; ++j) {
                int rk = ks * 16 + (lane & 15);
                int c = wn * 6 + j;
                uint32_t off = swzQ(rk, c);
                ldsm_x2t(vh[j], kb + 24576 + off);
                ldsm_x2t(vl[j], kb + 36864 + off);
            }
#pragma unroll
            for (int ti = 0; ti < 2; ++ti)
#pragma unroll
                for (int j = 0; j < 6; ++j)
                    mma_f32(acc[ti][j], ph[ti], vh[j]);
#pragma unroll
            for (int ti = 0; ti < 2; ++ti)
#pragma unroll
                for (int j = 0; j < 6; ++j)
                    mma_f16(&accx[ti][j].x, ph[ti], vl[j]);
#pragma unroll
            for (int ti = 0; ti < 2; ++ti)
#pragma unroll
                for (int j = 0; j < 6; ++j)
                    mma_f16(&accx[ti][j].x, pl[ti], vh[j]);
        }
        // drain cross into fp32 acc (before next kt's rescale)
#pragma unroll
        for (int ti = 0; ti < 2; ++ti)
#pragma unroll
            for (int j = 0; j < 6; ++j) {
                drain_h2(accx[ti][j].x, acc[ti][j][0], acc[ti][j][1]);
                drain_h2(accx[ti][j].y, acc[ti][j][2], acc[ti][j][3]);
            }
    }

    // ---- epilogue ----
    float inv[2][2];
#pragma unroll
    for (int ti = 0; ti < 2; ++ti)
#pragma unroll
        for (int hh = 0; hh < 2; ++hh)
            inv[ti][hh] = 1.f / l_run[ti][hh];

#pragma unroll
    for (int ti = 0; ti < 2; ++ti)
#pragma unroll
        for (int j = 0; j < 6; ++j) {
            int col = wn * 48 + j * 8 + (lane & 3) * 2;
            if (col >= HD) continue;
#pragma unroll
            for (int hh = 0; hh < 2; ++hh) {
                int s = q0 + wm * 32 + ti * 16 + hh * 8 + (lane >> 2);
                if (s >= SS) continue;
                float o0 = acc[ti][j][hh * 2] * inv[ti][hh];
                float o1 = acc[ti][j][hh * 2 + 1] * inv[ti][hh];
                uint32_t hi, lo;
                split_pair(o0, o1, hi, lo);
                size_t off = (size_t)(b * SS + s) * KK + (size_t)h * HD + col;
                *(uint32_t*)&attH[off] = hi;
                *(uint32_t*)&attL[off] = lo;
            }
        }
}

// ---------------------------------------------------------------------------
extern "C" void kernel_launch(void* const* d_in, const int* in_sizes, int n_in,
                              void* d_out, int out_size)
{
    const float* hs     = (const float*)d_in[0];
    const float* w_qkv  = (const float*)d_in[1];
    const float* b_qkv  = (const float*)d_in[2];
    const float* w_proj = (const float*)d_in[3];
    const float* b_proj = (const float*)d_in[4];
    float* out = (float*)d_out;

    __half *hsH, *hsL, *qkvH, *qkvL, *attH, *attL, *wqH, *wqL, *wpH, *wpL;
    cudaGetSymbolAddress((void**)&hsH, g_hsH);
    cudaGetSymbolAddress((void**)&hsL, g_hsL);
    cudaGetSymbolAddress((void**)&qkvH, g_qkvH);
    cudaGetSymbolAddress((void**)&qkvL, g_qkvL);
    cudaGetSymbolAddress((void**)&attH, g_attH);
    cudaGetSymbolAddress((void**)&attL, g_attL);
    cudaGetSymbolAddress((void**)&wqH, g_wqkvH);
    cudaGetSymbolAddress((void**)&wqL, g_wqkvL);
    cudaGetSymbolAddress((void**)&wpH, g_wprojH);
    cudaGetSymbolAddress((void**)&wpL, g_wprojL);

    const int gemm_smem = STAGES * STAGE_BYTES;   // 96 KB
    cudaFuncSetAttribute(gemm_mma_kernel<0>, cudaFuncAttributeMaxDynamicSharedMemorySize, gemm_smem);
    cudaFuncSetAttribute(gemm_mma_kernel<1>, cudaFuncAttributeMaxDynamicSharedMemorySize, gemm_smem);
    cudaFuncSetAttribute(attn_tc_kernel, cudaFuncAttributeMaxDynamicSharedMemorySize, SM_ATT_TOTAL);

    // 0a) split hidden_states
    {
        int n4 = MM * KK / 4;
        split_kernel<<<(n4 + 255) / 256, 256>>>((const float4*)hs, (uint2*)hsH, (uint2*)hsL, n4);
    }
    // 0b) transpose+split weights
    {
        dim3 g(N1 / 32, KK / 32);
        tsplit_kernel<<<g, dim3(32, 8)>>>(w_qkv, wqH, wqL, KK, N1);
    }
    {
        dim3 g(DD / 32, KK / 32);
        tsplit_kernel<<<g, dim3(32, 8)>>>(w_proj, wpH, wpL, KK, DD);
    }
    // 1) QKV projection -> fp16 hi/lo (q pre-scaled)
    {
        dim3 g(N1 / 128, (MM + 127) / 128);
        gemm_mma_kernel<1><<<g, 256, gemm_smem>>>(hsH, hsL, wqH, wqL, b_qkv,
                                                  nullptr, qkvH, qkvL, MM, N1);
    }
    // 2) tensor-core flash attention -> fp16 hi/lo
    {
        dim3 g((SS + 127) / 128, HH, BB);
        attn_tc_kernel<<<g, 256, SM_ATT_TOTAL>>>(qkvH, qkvL, attH, attL);
    }
    // 3) output projection -> fp32
    {
        dim3 g(DD / 128, (MM + 127) / 128);
        gemm_mma_kernel<0><<<g, 256, gemm_smem>>>(attH, attL, wpH, wpL, b_proj,
                                                  out, nullptr, nullptr, MM, DD);
    }
}

// round 9
// speedup vs baseline: 1.5745x; 1.5745x over previous
#include <cuda_runtime.h>
#include <cuda_fp16.h>
#include <cstdint>

// Problem constants
#define BB   16
#define SS   577
#define DD   1408
#define HH   16
#define HD   88
#define SCALE_F 0.10660035817780521f  // 1/sqrt(88)

#define MM   (BB * SS)      // 9232
#define N1   (3 * DD)       // 4224
#define KK   DD             // 1408

// ---------------------------------------------------------------------------
// Device-global scratch
// ---------------------------------------------------------------------------
__device__ __half g_hsH[(size_t)MM * KK];
__device__ __half g_hsL[(size_t)MM * KK];
__device__ __half g_qkv[(size_t)MM * N1];       // single fp16 (attention is 1-term)
__device__ __half g_attH[(size_t)MM * KK];
__device__ __half g_attL[(size_t)MM * KK];
__device__ __half g_wqkv[(size_t)N1 * KK];      // transposed [N,K], plain fp16
__device__ __half g_wproj[(size_t)DD * KK];     // transposed [N,K], plain fp16

// ---------------------------------------------------------------------------
// PTX helpers (sm_80+ only; harness targets sm_103 w/o 'a' — no tcgen05)
// ---------------------------------------------------------------------------
__device__ __forceinline__ uint32_t smem_to_u32(const void* p) {
    uint32_t a;
    asm("{ .reg .u64 t; cvta.to.shared.u64 t, %1; cvt.u32.u64 %0, t; }"
        : "=r"(a) : "l"(p));
    return a;
}
__device__ __forceinline__ void cp16(uint32_t dst, const void* src, uint32_t sz) {
    asm volatile("cp.async.ca.shared.global [%0], [%1], 16, %2;"
                 :: "r"(dst), "l"(src), "r"(sz) : "memory");
}
#define CP_COMMIT() asm volatile("cp.async.commit_group;" ::: "memory")
#define CP_WAIT(n)  asm volatile("cp.async.wait_group %0;" :: "n"(n) : "memory")

__device__ __forceinline__ void ldsm_x4(uint32_t* r, uint32_t addr) {
    asm volatile("ldmatrix.sync.aligned.m8n8.x4.shared.b16 {%0,%1,%2,%3}, [%4];"
                 : "=r"(r[0]), "=r"(r[1]), "=r"(r[2]), "=r"(r[3]) : "r"(addr));
}
__device__ __forceinline__ void ldsm_x2(uint32_t* r, uint32_t addr) {
    asm volatile("ldmatrix.sync.aligned.m8n8.x2.shared.b16 {%0,%1}, [%2];"
                 : "=r"(r[0]), "=r"(r[1]) : "r"(addr));
}
__device__ __forceinline__ void ldsm_x2t(uint32_t* r, uint32_t addr) {
    asm volatile("ldmatrix.sync.aligned.m8n8.x2.trans.shared.b16 {%0,%1}, [%2];"
                 : "=r"(r[0]), "=r"(r[1]) : "r"(addr));
}
__device__ __forceinline__ void mma_f32(float* d, const uint32_t* a, const uint32_t* b) {
    asm volatile("mma.sync.aligned.m16n8k16.row.col.f32.f16.f16.f32 "
                 "{%0,%1,%2,%3}, {%4,%5,%6,%7}, {%8,%9}, {%0,%1,%2,%3};"
                 : "+f"(d[0]), "+f"(d[1]), "+f"(d[2]), "+f"(d[3])
                 : "r"(a[0]), "r"(a[1]), "r"(a[2]), "r"(a[3]), "r"(b[0]), "r"(b[1]));
}
__device__ __forceinline__ void split_pair(float a, float b, uint32_t& hi, uint32_t& lo) {
    __half ha = __float2half_rn(a), hb = __float2half_rn(b);
    float la = a - __half2float(ha), lb = b - __half2float(hb);
    __half hla = __float2half_rn(la), hlb = __float2half_rn(lb);
    hi = ((uint32_t)__half_as_ushort(hb) << 16) | __half_as_ushort(ha);
    lo = ((uint32_t)__half_as_ushort(hlb) << 16) | __half_as_ushort(hla);
}
__device__ __forceinline__ uint32_t pack_h2(float a, float b) {
    __half2 h = __floats2half2_rn(a, b);
    return *reinterpret_cast<uint32_t*>(&h);
}

// ---------------------------------------------------------------------------
// Split fp32 -> (hi, lo) fp16, same layout.
// ---------------------------------------------------------------------------
__global__ void split_kernel(const float4* __restrict__ in,
                             uint2* __restrict__ hi, uint2* __restrict__ lo, int n4)
{
    int i = blockIdx.x * blockDim.x + threadIdx.x;
    if (i >= n4) return;
    float4 v = in[i];
    uint2 ho, loo;
    split_pair(v.x, v.y, ho.x, loo.x);
    split_pair(v.z, v.w, ho.y, loo.y);
    hi[i] = ho;
    lo[i] = loo;
}

// ---------------------------------------------------------------------------
// Transpose + round: in fp32 [R, C] -> fp16 [C, R]
// ---------------------------------------------------------------------------
__global__ void ttrunc_kernel(const float* __restrict__ in,
                              __half* __restrict__ out, int R, int C)
{
    __shared__ float t[32][33];
    int c0 = blockIdx.x * 32, r0 = blockIdx.y * 32;
    int tx = threadIdx.x, ty = threadIdx.y;
#pragma unroll
    for (int i = ty; i < 32; i += 8)
        t[i][tx] = in[(size_t)(r0 + i) * C + c0 + tx];
    __syncthreads();
#pragma unroll
    for (int i = ty; i < 32; i += 8)
        out[(size_t)(c0 + i) * R + r0 + tx] = __float2half_rn(t[tx][i]);
}

// ---------------------------------------------------------------------------
// 2-term fp16 GEMM: C[M,N] = (Ahi+Alo)[M,K] @ B[N,K]^T + bias[N]
// A split hi/lo fp16 (both terms fp32-accum into SAME accumulator);
// B plain fp16 (weight rounding is the error floor, ~2.4e-4 RMS).
// CTA 128x128, BK=32, 3 stages (72 KB), 8 warps (4M x 2N).
// MODE 0: fp32 C out.  MODE 1: single fp16 out, cols<DD scaled by SCALE_F.
// ---------------------------------------------------------------------------
#define BK      32
#define STAGES  3
#define TBYTES  8192
#define STAGE_BYTES (3 * TBYTES)
#define NCH     (KK / BK)

__device__ __forceinline__ uint32_t swz(int r, int c) {
    return (uint32_t)(r * 64 + ((c ^ ((r >> 1) & 3)) << 4));
}

template<int MODE>
__global__ __launch_bounds__(256, 1) void gemm_mma_kernel(
    const __half* __restrict__ Ahi, const __half* __restrict__ Alo,
    const __half* __restrict__ B,
    const float* __restrict__ bias, float* __restrict__ C,
    __half* __restrict__ CH, int M, int N)
{
    extern __shared__ char smem[];
    const uint32_t sbase = smem_to_u32(smem);

    const int tid = threadIdx.x;
    const int lane = tid & 31;
    const int wid = tid >> 5;
    const int wm = wid & 3;
    const int wn = wid >> 2;
    const int m0 = blockIdx.y * 128;
    const int n0 = blockIdx.x * 128;

    auto load_stage = [&](int kt, int slot) {
        const int k0 = kt * BK;
        const uint32_t st = sbase + slot * STAGE_BYTES;
#pragma unroll
        for (int i = 0; i < 6; ++i) {
            int idx = tid + i * 256;       // 0..1535
            int tile = idx >> 9;           // 0:Ah 1:Al 2:B
            int rem = idx & 511;
            int r = rem >> 2;
            int c = rem & 3;
            uint32_t dst = st + tile * TBYTES + swz(r, c);
            const __half* gp;
            uint32_t sz = 16;
            if (tile < 2) {
                int m = m0 + r;
                int mc = m < M ? m : 0;
                if (m >= M) sz = 0;
                gp = (tile == 0 ? Ahi : Alo) + (size_t)mc * KK + k0 + c * 8;
            } else {
                int n = n0 + r;
                gp = B + (size_t)n * KK + k0 + c * 8;
            }
            cp16(dst, gp, sz);
        }
        CP_COMMIT();
    };

    float acc[2][8][4];
#pragma unroll
    for (int t = 0; t < 2; ++t)
#pragma unroll
        for (int j = 0; j < 8; ++j)
#pragma unroll
            for (int v = 0; v < 4; ++v) acc[t][j][v] = 0.f;

    load_stage(0, 0);
    load_stage(1, 1);

    const int ar[2] = { wm * 32 + (lane & 15), wm * 32 + 16 + (lane & 15) };
    const int acl = (lane >> 4);
    const int br = wn * 64 + (lane & 7) + ((lane >> 4) & 1) * 8;
    const int bcl = (lane >> 3) & 1;

    for (int kt = 0; kt < NCH; ++kt) {
        CP_WAIT(1);
        __syncthreads();
        if (kt + 2 < NCH) load_stage(kt + 2, (kt + 2) % STAGES);

        const uint32_t st = sbase + (kt % STAGES) * STAGE_BYTES;
#pragma unroll
        for (int ks = 0; ks < 2; ++ks) {
            uint32_t ah[2][4], al[2][4], b[4][4];
#pragma unroll
            for (int t = 0; t < 2; ++t)
                ldsm_x4(ah[t], st + 0 * TBYTES + swz(ar[t], ks * 2 + acl));
#pragma unroll
            for (int jj = 0; jj < 4; ++jj)
                ldsm_x4(b[jj], st + 2 * TBYTES + swz(br + jj * 16, ks * 2 + bcl));
            // term 1: Ah * B
#pragma unroll
            for (int t = 0; t < 2; ++t)
#pragma unroll
                for (int jj = 0; jj < 4; ++jj) {
                    mma_f32(acc[t][jj * 2 + 0], ah[t], &b[jj][0]);
                    mma_f32(acc[t][jj * 2 + 1], ah[t], &b[jj][2]);
                }
            // term 2: Al * B (same accumulators)
#pragma unroll
            for (int t = 0; t < 2; ++t)
                ldsm_x4(al[t], st + 1 * TBYTES + swz(ar[t], ks * 2 + acl));
#pragma unroll
            for (int t = 0; t < 2; ++t)
#pragma unroll
                for (int jj = 0; jj < 4; ++jj) {
                    mma_f32(acc[t][jj * 2 + 0], al[t], &b[jj][0]);
                    mma_f32(acc[t][jj * 2 + 1], al[t], &b[jj][2]);
                }
        }
    }

    const int rb = m0 + wm * 32 + (lane >> 2);
    const int cb = n0 + wn * 64 + (lane & 3) * 2;
#pragma unroll
    for (int t = 0; t < 2; ++t) {
        int r0 = rb + t * 16;
#pragma unroll
        for (int j = 0; j < 8; ++j) {
            int col = cb + j * 8;
            float2 b2 = *(const float2*)&bias[col];
            if constexpr (MODE == 0) {
                if (r0 < M) {
                    float2 o = {acc[t][j][0] + b2.x, acc[t][j][1] + b2.y};
                    *(float2*)&C[(size_t)r0 * N + col] = o;
                }
                if (r0 + 8 < M) {
                    float2 o = {acc[t][j][2] + b2.x, acc[t][j][3] + b2.y};
                    *(float2*)&C[(size_t)(r0 + 8) * N + col] = o;
                }
            } else {
                float s = (col < DD) ? SCALE_F : 1.0f;
                if (r0 < M)
                    *(uint32_t*)&CH[(size_t)r0 * N + col] =
                        pack_h2((acc[t][j][0] + b2.x) * s, (acc[t][j][1] + b2.y) * s);
                if (r0 + 8 < M)
                    *(uint32_t*)&CH[(size_t)(r0 + 8) * N + col] =
                        pack_h2((acc[t][j][2] + b2.x) * s, (acc[t][j][3] + b2.y) * s);
            }
        }
    }
}

// ---------------------------------------------------------------------------
// Tensor-core flash attention, plain fp16 (1 MMA per product, fp32 accum).
// smem: Q 24KB | KV 2x24KB | P 16KB | stats 2KB = 90KB -> 2 CTAs/SM.
// Epilogue writes fp16 hi/lo split (GEMM2 input).
// ---------------------------------------------------------------------------
#define SM_Q    0
#define SM_KV   24576            // buf stride 24576: K@0, V@12288
#define SM_P    73728
#define SM_STAT 90112            // sMax[2][128] f32, sSum[2][128] f32
#define SM_ATT_TOTAL 92160

__device__ __forceinline__ uint32_t swzQ(int r, int c) {
    return (uint32_t)(r * 192 + ((c ^ ((r >> 1) & 3)) << 4));
}
__device__ __forceinline__ uint32_t swzP(int r, int c) {
    return (uint32_t)(r * 128 + ((c ^ (r & 7)) << 4));
}

__global__ __launch_bounds__(256, 2) void attn_tc_kernel(
    const __half* __restrict__ qkv,
    __half* __restrict__ attH, __half* __restrict__ attL)
{
    extern __shared__ char smem[];
    const uint32_t sb = smem_to_u32(smem);
    const int tid = threadIdx.x;
    const int lane = tid & 31;
    const int wid = tid >> 5;
    const int wm = wid & 3;
    const int wn = wid >> 2;
    const int b = blockIdx.z;
    const int h = blockIdx.y;
    const int q0 = blockIdx.x * 128;

    float* sMax = (float*)(smem + SM_STAT);
    float* sSum = (float*)(smem + SM_STAT + 1024);

    const size_t rowbase = (size_t)b * SS * N1 + (size_t)h * HD;

    // Q: 128 rows x 12 chunks; 2 threads/row, 6 chunks each
    {
        int r = tid >> 1;
        int cbase = (tid & 1) * 6;
        int s = q0 + r;
        int sc_ = s < SS ? s : SS - 1;
        const __half* src = qkv + rowbase + (size_t)sc_ * N1;
#pragma unroll
        for (int cc = 0; cc < 6; ++cc) {
            int c = cbase + cc;
            int ca = c < 11 ? c : 10;
            uint32_t sz = (c < 11 && s < SS) ? 16 : 0;
            cp16(sb + SM_Q + swzQ(r, c), src + ca * 8, sz);
        }
    }

    // KV: 64 rows x 12 chunks x 2 arrays (K,V); 4 threads/row, 3 chunks x 2
    auto load_kv = [&](int kt, int buf) {
        int r = tid >> 2;
        int cbase = (tid & 3) * 3;
        int s = kt * 64 + r;
        int sc_ = s < SS ? s : SS - 1;
        const uint32_t kb = sb + SM_KV + buf * 24576;
        const __half* baseK = qkv + rowbase + (size_t)sc_ * N1 + DD;
        const __half* baseV = qkv + rowbase + (size_t)sc_ * N1 + 2 * DD;
#pragma unroll
        for (int cc = 0; cc < 3; ++cc) {
            int c = cbase + cc;
            int ca = c < 11 ? c : 10;
            uint32_t sz = (c < 11 && s < SS) ? 16 : 0;
            cp16(kb + swzQ(r, c), baseK + ca * 8, sz);
            cp16(kb + 12288 + swzQ(r, c), baseV + ca * 8, sz);
        }
    };

    load_kv(0, 0);
    CP_COMMIT();

    float acc[2][6][4];
#pragma unroll
    for (int ti = 0; ti < 2; ++ti)
#pragma unroll
        for (int j = 0; j < 6; ++j)
#pragma unroll
            for (int v = 0; v < 4; ++v) acc[ti][j][v] = 0.f;
    float m_old[2][2] = {{-1e30f, -1e30f}, {-1e30f, -1e30f}};
    float l_run[2][2] = {{0.f, 0.f}, {0.f, 0.f}};

    const int NKT = (SS + 63) / 64;

    for (int kt = 0; kt < NKT; ++kt) {
        CP_WAIT(0);
        __syncthreads();
        if (kt + 1 < NKT) load_kv(kt + 1, (kt + 1) & 1);
        CP_COMMIT();

        const uint32_t kb = sb + SM_KV + (kt & 1) * 24576;

        // ---- QK^T (1 term) ----
        float sc[2][4][4];
#pragma unroll
        for (int ti = 0; ti < 2; ++ti)
#pragma unroll
            for (int j = 0; j < 4; ++j)
#pragma unroll
                for (int v = 0; v < 4; ++v) sc[ti][j][v] = 0.f;

#pragma unroll
        for (int ks = 0; ks < 6; ++ks) {
            uint32_t a[2][4], bq[4][2];
#pragma unroll
            for (int ti = 0; ti < 2; ++ti) {
                int r = wm * 32 + ti * 16 + (lane & 15);
                int c = ks * 2 + (lane >> 4);
                ldsm_x4(a[ti], sb + SM_Q + swzQ(r, c));
            }
#pragma unroll
            for (int j = 0; j < 4; ++j) {
                int r = wn * 32 + j * 8 + (lane & 7);
                int c = ks * 2 + ((lane >> 3) & 1);
                ldsm_x2(bq[j], kb + swzQ(r, c));
            }
#pragma unroll
            for (int ti = 0; ti < 2; ++ti)
#pragma unroll
                for (int j = 0; j < 4; ++j)
                    mma_f32(sc[ti][j], a[ti], bq[j]);
        }

        // ---- mask ----
#pragma unroll
        for (int j = 0; j < 4; ++j) {
            int c0 = kt * 64 + wn * 32 + j * 8 + (lane & 3) * 2;
            if (c0 >= SS) { sc[0][j][0] = sc[0][j][2] = sc[1][j][0] = sc[1][j][2] = -1e30f; }
            if (c0 + 1 >= SS) { sc[0][j][1] = sc[0][j][3] = sc[1][j][1] = sc[1][j][3] = -1e30f; }
        }

        // ---- row max (cross-warp via smem) ----
#pragma unroll
        for (int ti = 0; ti < 2; ++ti)
#pragma unroll
            for (int hh = 0; hh < 2; ++hh) {
                float mt = -1e30f;
#pragma unroll
                for (int j = 0; j < 4; ++j)
                    mt = fmaxf(mt, fmaxf(sc[ti][j][hh * 2], sc[ti][j][hh * 2 + 1]));
                mt = fmaxf(mt, __shfl_xor_sync(0xffffffffu, mt, 1));
                mt = fmaxf(mt, __shfl_xor_sync(0xffffffffu, mt, 2));
                if ((lane & 3) == 0) {
                    int rl = wm * 32 + ti * 16 + hh * 8 + (lane >> 2);
                    sMax[wn * 128 + rl] = mt;
                }
            }
        __syncthreads();

        float mnew[2][2], corr[2][2];
#pragma unroll
        for (int ti = 0; ti < 2; ++ti)
#pragma unroll
            for (int hh = 0; hh < 2; ++hh) {
                int rl = wm * 32 + ti * 16 + hh * 8 + (lane >> 2);
                float m2 = fmaxf(sMax[rl], sMax[128 + rl]);
                float mn = fmaxf(m_old[ti][hh], m2);
                corr[ti][hh] = __expf(m_old[ti][hh] - mn);
                mnew[ti][hh] = mn;
                m_old[ti][hh] = mn;
            }

        // ---- exp, P store (fp16), sums ----
        float sum_[2][2] = {{0.f, 0.f}, {0.f, 0.f}};
#pragma unroll
        for (int ti = 0; ti < 2; ++ti) {
            int r0 = wm * 32 + ti * 16 + (lane >> 2);
#pragma unroll
            for (int j = 0; j < 4; ++j) {
                float p0 = __expf(sc[ti][j][0] - mnew[ti][0]);
                float p1 = __expf(sc[ti][j][1] - mnew[ti][0]);
                float p2 = __expf(sc[ti][j][2] - mnew[ti][1]);
                float p3 = __expf(sc[ti][j][3] - mnew[ti][1]);
                sum_[ti][0] += p0 + p1;
                sum_[ti][1] += p2 + p3;
                int colc = wn * 32 + j * 8 + (lane & 3) * 2;
                uint32_t o0 = swzP(r0, colc >> 3) + (colc & 7) * 2;
                uint32_t o1 = swzP(r0 + 8, colc >> 3) + (colc & 7) * 2;
                *(uint32_t*)(smem + SM_P + o0) = pack_h2(p0, p1);
                *(uint32_t*)(smem + SM_P + o1) = pack_h2(p2, p3);
            }
        }
#pragma unroll
        for (int ti = 0; ti < 2; ++ti)
#pragma unroll
            for (int hh = 0; hh < 2; ++hh) {
                float s = sum_[ti][hh];
                s += __shfl_xor_sync(0xffffffffu, s, 1);
                s += __shfl_xor_sync(0xffffffffu, s, 2);
                if ((lane & 3) == 0) {
                    int rl = wm * 32 + ti * 16 + hh * 8 + (lane >> 2);
                    sSum[wn * 128 + rl] = s;
                }
            }
#pragma unroll
        for (int ti = 0; ti < 2; ++ti)
#pragma unroll
            for (int j = 0; j < 6; ++j) {
                acc[ti][j][0] *= corr[ti][0];
                acc[ti][j][1] *= corr[ti][0];
                acc[ti][j][2] *= corr[ti][1];
                acc[ti][j][3] *= corr[ti][1];
            }
        __syncthreads();
#pragma unroll
        for (int ti = 0; ti < 2; ++ti)
#pragma unroll
            for (int hh = 0; hh < 2; ++hh) {
                int rl = wm * 32 + ti * 16 + hh * 8 + (lane >> 2);
                l_run[ti][hh] = l_run[ti][hh] * corr[ti][hh] + sSum[rl] + sSum[128 + rl];
            }

        // ---- P.V (1 term) ----
#pragma unroll
        for (int ks = 0; ks < 4; ++ks) {
            uint32_t p[2][4], v[6][2];
#pragma unroll
            for (int ti = 0; ti < 2; ++ti) {
                int r = wm * 32 + ti * 16 + (lane & 15);
                int c = ks * 2 + (lane >> 4);
                ldsm_x4(p[ti], sb + SM_P + swzP(r, c));
            }
#pragma unroll
            for (int j = 0; j < 6; ++j) {
                int rk = ks * 16 + (lane & 15);
                int c = wn * 6 + j;
                ldsm_x2t(v[j], kb + 12288 + swzQ(rk, c));
            }
#pragma unroll
            for (int ti = 0; ti < 2; ++ti)
#pragma unroll
                for (int j = 0; j < 6; ++j)
                    mma_f32(acc[ti][j], p[ti], v[j]);
        }
    }

    // ---- epilogue: normalize, fp16 hi/lo split, store ----
    float inv[2][2];
#pragma unroll
    for (int ti = 0; ti < 2; ++ti)
#pragma unroll
        for (int hh = 0; hh < 2; ++hh)
            inv[ti][hh] = 1.f / l_run[ti][hh];

#pragma unroll
    for (int ti = 0; ti < 2; ++ti)
#pragma unroll
        for (int j = 0; j < 6; ++j) {
            int col = wn * 48 + j * 8 + (lane & 3) * 2;
            if (col >= HD) continue;
#pragma unroll
            for (int hh = 0; hh < 2; ++hh) {
                int s = q0 + wm * 32 + ti * 16 + hh * 8 + (lane >> 2);
                if (s >= SS) continue;
                float o0 = acc[ti][j][hh * 2] * inv[ti][hh];
                float o1 = acc[ti][j][hh * 2 + 1] * inv[ti][hh];
                uint32_t hi, lo;
                split_pair(o0, o1, hi, lo);
                size_t off = (size_t)(b * SS + s) * KK + (size_t)h * HD + col;
                *(uint32_t*)&attH[off] = hi;
                *(uint32_t*)&attL[off] = lo;
            }
        }
}

// ---------------------------------------------------------------------------
extern "C" void kernel_launch(void* const* d_in, const int* in_sizes, int n_in,
                              void* d_out, int out_size)
{
    const float* hs     = (const float*)d_in[0];
    const float* w_qkv  = (const float*)d_in[1];
    const float* b_qkv  = (const float*)d_in[2];
    const float* w_proj = (const float*)d_in[3];
    const float* b_proj = (const float*)d_in[4];
    float* out = (float*)d_out;

    __half *hsH, *hsL, *qkv, *attH, *attL, *wq, *wp;
    cudaGetSymbolAddress((void**)&hsH, g_hsH);
    cudaGetSymbolAddress((void**)&hsL, g_hsL);
    cudaGetSymbolAddress((void**)&qkv, g_qkv);
    cudaGetSymbolAddress((void**)&attH, g_attH);
    cudaGetSymbolAddress((void**)&attL, g_attL);
    cudaGetSymbolAddress((void**)&wq, g_wqkv);
    cudaGetSymbolAddress((void**)&wp, g_wproj);

    const int gemm_smem = STAGES * STAGE_BYTES;   // 72 KB
    cudaFuncSetAttribute(gemm_mma_kernel<0>, cudaFuncAttributeMaxDynamicSharedMemorySize, gemm_smem);
    cudaFuncSetAttribute(gemm_mma_kernel<1>, cudaFuncAttributeMaxDynamicSharedMemorySize, gemm_smem);
    cudaFuncSetAttribute(attn_tc_kernel, cudaFuncAttributeMaxDynamicSharedMemorySize, SM_ATT_TOTAL);

    // 0a) split hidden_states (hi/lo fp16)
    {
        int n4 = MM * KK / 4;
        split_kernel<<<(n4 + 255) / 256, 256>>>((const float4*)hs, (uint2*)hsH, (uint2*)hsL, n4);
    }
    // 0b) transpose+round weights to fp16
    {
        dim3 g(N1 / 32, KK / 32);
        ttrunc_kernel<<<g, dim3(32, 8)>>>(w_qkv, wq, KK, N1);
    }
    {
        dim3 g(DD / 32, KK / 32);
        ttrunc_kernel<<<g, dim3(32, 8)>>>(w_proj, wp, KK, DD);
    }
    // 1) QKV projection (2-term) -> single fp16 (q pre-scaled)
    {
        dim3 g(N1 / 128, (MM + 127) / 128);
        gemm_mma_kernel<1><<<g, 256, gemm_smem>>>(hsH, hsL, wq, b_qkv,
                                                  nullptr, qkv, MM, N1);
    }
    // 2) flash attention (1-term fp16) -> fp16 hi/lo
    {
        dim3 g((SS + 127) / 128, HH, BB);
        attn_tc_kernel<<<g, 256, SM_ATT_TOTAL>>>(qkv, attH, attL);
    }
    // 3) output projection (2-term) -> fp32
    {
        dim3 g(DD / 128, (MM + 127) / 128);
        gemm_mma_kernel<0><<<g, 256, gemm_smem>>>(attH, attL, wp, b_proj,
                                                  out, nullptr, MM, DD);
    }
}

// round 10
// speedup vs baseline: 2.2715x; 1.4427x over previous
#include <cuda_runtime.h>
#include <cuda_fp16.h>
#include <cstdint>

// Problem constants
#define BB   16
#define SS   577
#define DD   1408
#define HH   16
#define HD   88
#define SCALE_F 0.10660035817780521f  // 1/sqrt(88)

#define MM   (BB * SS)      // 9232
#define N1   (3 * DD)       // 4224
#define KK   DD             // 1408

// ---------------------------------------------------------------------------
// Device-global scratch
// ---------------------------------------------------------------------------
__device__ __half g_hs[(size_t)MM * KK];        // plain fp16 (GEMM1 is 1-term)
__device__ __half g_qkv[(size_t)MM * N1];       // single fp16
__device__ __half g_attH[(size_t)MM * KK];      // hi/lo split (GEMM2 is 2-term)
__device__ __half g_attL[(size_t)MM * KK];
__device__ __half g_wqkv[(size_t)N1 * KK];      // transposed [N,K], plain fp16
__device__ __half g_wproj[(size_t)DD * KK];     // transposed [N,K], plain fp16

// ---------------------------------------------------------------------------
// PTX helpers (sm_80+ only; harness targets sm_103 w/o 'a' — no tcgen05)
// ---------------------------------------------------------------------------
__device__ __forceinline__ uint32_t smem_to_u32(const void* p) {
    uint32_t a;
    asm("{ .reg .u64 t; cvta.to.shared.u64 t, %1; cvt.u32.u64 %0, t; }"
        : "=r"(a) : "l"(p));
    return a;
}
__device__ __forceinline__ void cp16(uint32_t dst, const void* src, uint32_t sz) {
    asm volatile("cp.async.ca.shared.global [%0], [%1], 16, %2;"
                 :: "r"(dst), "l"(src), "r"(sz) : "memory");
}
#define CP_COMMIT() asm volatile("cp.async.commit_group;" ::: "memory")
#define CP_WAIT(n)  asm volatile("cp.async.wait_group %0;" :: "n"(n) : "memory")

__device__ __forceinline__ void ldsm_x4(uint32_t* r, uint32_t addr) {
    asm volatile("ldmatrix.sync.aligned.m8n8.x4.shared.b16 {%0,%1,%2,%3}, [%4];"
                 : "=r"(r[0]), "=r"(r[1]), "=r"(r[2]), "=r"(r[3]) : "r"(addr));
}
__device__ __forceinline__ void ldsm_x2(uint32_t* r, uint32_t addr) {
    asm volatile("ldmatrix.sync.aligned.m8n8.x2.shared.b16 {%0,%1}, [%2];"
                 : "=r"(r[0]), "=r"(r[1]) : "r"(addr));
}
__device__ __forceinline__ void ldsm_x2t(uint32_t* r, uint32_t addr) {
    asm volatile("ldmatrix.sync.aligned.m8n8.x2.trans.shared.b16 {%0,%1}, [%2];"
                 : "=r"(r[0]), "=r"(r[1]) : "r"(addr));
}
__device__ __forceinline__ void mma_f32(float* d, const uint32_t* a, const uint32_t* b) {
    asm volatile("mma.sync.aligned.m16n8k16.row.col.f32.f16.f16.f32 "
                 "{%0,%1,%2,%3}, {%4,%5,%6,%7}, {%8,%9}, {%0,%1,%2,%3};"
                 : "+f"(d[0]), "+f"(d[1]), "+f"(d[2]), "+f"(d[3])
                 : "r"(a[0]), "r"(a[1]), "r"(a[2]), "r"(a[3]), "r"(b[0]), "r"(b[1]));
}
__device__ __forceinline__ void split_pair(float a, float b, uint32_t& hi, uint32_t& lo) {
    __half ha = __float2half_rn(a), hb = __float2half_rn(b);
    float la = a - __half2float(ha), lb = b - __half2float(hb);
    __half hla = __float2half_rn(la), hlb = __float2half_rn(lb);
    hi = ((uint32_t)__half_as_ushort(hb) << 16) | __half_as_ushort(ha);
    lo = ((uint32_t)__half_as_ushort(hlb) << 16) | __half_as_ushort(hla);
}
__device__ __forceinline__ uint32_t pack_h2(float a, float b) {
    __half2 h = __floats2half2_rn(a, b);
    return *reinterpret_cast<uint32_t*>(&h);
}

// ---------------------------------------------------------------------------
// Round fp32 -> fp16, same layout.
// ---------------------------------------------------------------------------
__global__ void round_kernel(const float4* __restrict__ in,
                             uint2* __restrict__ out, int n4)
{
    int i = blockIdx.x * blockDim.x + threadIdx.x;
    if (i >= n4) return;
    float4 v = in[i];
    uint2 o;
    o.x = pack_h2(v.x, v.y);
    o.y = pack_h2(v.z, v.w);
    out[i] = o;
}

// ---------------------------------------------------------------------------
// Transpose + round: in fp32 [R, C] -> fp16 [C, R]
// ---------------------------------------------------------------------------
__global__ void ttrunc_kernel(const float* __restrict__ in,
                              __half* __restrict__ out, int R, int C)
{
    __shared__ float t[32][33];
    int c0 = blockIdx.x * 32, r0 = blockIdx.y * 32;
    int tx = threadIdx.x, ty = threadIdx.y;
#pragma unroll
    for (int i = ty; i < 32; i += 8)
        t[i][tx] = in[(size_t)(r0 + i) * C + c0 + tx];
    __syncthreads();
#pragma unroll
    for (int i = ty; i < 32; i += 8)
        out[(size_t)(c0 + i) * R + r0 + tx] = __float2half_rn(t[tx][i]);
}

// ---------------------------------------------------------------------------
// fp16 MMA GEMM: C[M,N] = A[M,K] @ B[N,K]^T + bias[N]
// TERMS=1: A plain fp16 (Alo unused).  TERMS=2: A = Ahi + Alo, both into
// the same fp32 accumulators. B always plain fp16.
// CTA 128x128, BK=32, 3 stages, 8 warps (4M x 2N).
// MODE 0: fp32 C out.  MODE 1: single fp16 out, cols<DD scaled by SCALE_F.
// ---------------------------------------------------------------------------
#define BK      32
#define STAGES  3
#define TBYTES  8192
#define NCH     (KK / BK)

__device__ __forceinline__ uint32_t swz(int r, int c) {
    return (uint32_t)(r * 64 + ((c ^ ((r >> 1) & 3)) << 4));
}

template<int MODE, int TERMS>
__global__ __launch_bounds__(256, 2) void gemm_mma_kernel(
    const __half* __restrict__ Ahi, const __half* __restrict__ Alo,
    const __half* __restrict__ B,
    const float* __restrict__ bias, float* __restrict__ C,
    __half* __restrict__ CH, int M, int N)
{
    constexpr uint32_t STG_BYTES = (TERMS + 1) * TBYTES;
    extern __shared__ char smem[];
    const uint32_t sbase = smem_to_u32(smem);

    const int tid = threadIdx.x;
    const int lane = tid & 31;
    const int wid = tid >> 5;
    const int wm = wid & 3;
    const int wn = wid >> 2;
    const int m0 = blockIdx.y * 128;
    const int n0 = blockIdx.x * 128;

    auto load_stage = [&](int kt, int slot) {
        const int k0 = kt * BK;
        const uint32_t st = sbase + slot * STG_BYTES;
#pragma unroll
        for (int i = 0; i < 2 * (TERMS + 1); ++i) {
            int idx = tid + i * 256;
            int tile = idx >> 9;           // 0..TERMS-1: A terms; TERMS: B
            int rem = idx & 511;
            int r = rem >> 2;
            int c = rem & 3;
            uint32_t dst = st + tile * TBYTES + swz(r, c);
            const __half* gp;
            uint32_t sz = 16;
            if (tile < TERMS) {
                int m = m0 + r;
                int mc = m < M ? m : 0;
                if (m >= M) sz = 0;
                gp = (tile == 0 ? Ahi : Alo) + (size_t)mc * KK + k0 + c * 8;
            } else {
                int n = n0 + r;
                gp = B + (size_t)n * KK + k0 + c * 8;
            }
            cp16(dst, gp, sz);
        }
        CP_COMMIT();
    };

    float acc[2][8][4];
#pragma unroll
    for (int t = 0; t < 2; ++t)
#pragma unroll
        for (int j = 0; j < 8; ++j)
#pragma unroll
            for (int v = 0; v < 4; ++v) acc[t][j][v] = 0.f;

    load_stage(0, 0);
    load_stage(1, 1);

    const int ar[2] = { wm * 32 + (lane & 15), wm * 32 + 16 + (lane & 15) };
    const int acl = (lane >> 4);
    const int br = wn * 64 + (lane & 7) + ((lane >> 4) & 1) * 8;
    const int bcl = (lane >> 3) & 1;

    for (int kt = 0; kt < NCH; ++kt) {
        CP_WAIT(1);
        __syncthreads();
        if (kt + 2 < NCH) load_stage(kt + 2, (kt + 2) % STAGES);

        const uint32_t st = sbase + (kt % STAGES) * STG_BYTES;
#pragma unroll
        for (int ks = 0; ks < 2; ++ks) {
            uint32_t ah[2][4], b[4][4];
#pragma unroll
            for (int t = 0; t < 2; ++t)
                ldsm_x4(ah[t], st + 0 * TBYTES + swz(ar[t], ks * 2 + acl));
#pragma unroll
            for (int jj = 0; jj < 4; ++jj)
                ldsm_x4(b[jj], st + TERMS * TBYTES + swz(br + jj * 16, ks * 2 + bcl));
#pragma unroll
            for (int t = 0; t < 2; ++t)
#pragma unroll
                for (int jj = 0; jj < 4; ++jj) {
                    mma_f32(acc[t][jj * 2 + 0], ah[t], &b[jj][0]);
                    mma_f32(acc[t][jj * 2 + 1], ah[t], &b[jj][2]);
                }
            if constexpr (TERMS == 2) {
                uint32_t al[2][4];
#pragma unroll
                for (int t = 0; t < 2; ++t)
                    ldsm_x4(al[t], st + 1 * TBYTES + swz(ar[t], ks * 2 + acl));
#pragma unroll
                for (int t = 0; t < 2; ++t)
#pragma unroll
                    for (int jj = 0; jj < 4; ++jj) {
                        mma_f32(acc[t][jj * 2 + 0], al[t], &b[jj][0]);
                        mma_f32(acc[t][jj * 2 + 1], al[t], &b[jj][2]);
                    }
            }
        }
    }

    const int rb = m0 + wm * 32 + (lane >> 2);
    const int cb = n0 + wn * 64 + (lane & 3) * 2;
#pragma unroll
    for (int t = 0; t < 2; ++t) {
        int r0 = rb + t * 16;
#pragma unroll
        for (int j = 0; j < 8; ++j) {
            int col = cb + j * 8;
            float2 b2 = *(const float2*)&bias[col];
            if constexpr (MODE == 0) {
                if (r0 < M) {
                    float2 o = {acc[t][j][0] + b2.x, acc[t][j][1] + b2.y};
                    *(float2*)&C[(size_t)r0 * N + col] = o;
                }
                if (r0 + 8 < M) {
                    float2 o = {acc[t][j][2] + b2.x, acc[t][j][3] + b2.y};
                    *(float2*)&C[(size_t)(r0 + 8) * N + col] = o;
                }
            } else {
                float s = (col < DD) ? SCALE_F : 1.0f;
                if (r0 < M)
                    *(uint32_t*)&CH[(size_t)r0 * N + col] =
                        pack_h2((acc[t][j][0] + b2.x) * s, (acc[t][j][1] + b2.y) * s);
                if (r0 + 8 < M)
                    *(uint32_t*)&CH[(size_t)(r0 + 8) * N + col] =
                        pack_h2((acc[t][j][2] + b2.x) * s, (acc[t][j][3] + b2.y) * s);
            }
        }
    }
}

// ---------------------------------------------------------------------------
// Tensor-core flash attention, plain fp16 (1 MMA per product, fp32 accum).
// smem: Q 24KB | KV 2x24KB | P 16KB | stats 2KB = 90KB -> 2 CTAs/SM.
// Epilogue writes fp16 hi/lo split (GEMM2 input).
// ---------------------------------------------------------------------------
#define SM_Q    0
#define SM_KV   24576            // buf stride 24576: K@0, V@12288
#define SM_P    73728
#define SM_STAT 90112
#define SM_ATT_TOTAL 92160

__device__ __forceinline__ uint32_t swzQ(int r, int c) {
    return (uint32_t)(r * 192 + ((c ^ ((r >> 1) & 3)) << 4));
}
__device__ __forceinline__ uint32_t swzP(int r, int c) {
    return (uint32_t)(r * 128 + ((c ^ (r & 7)) << 4));
}

__global__ __launch_bounds__(256, 2) void attn_tc_kernel(
    const __half* __restrict__ qkv,
    __half* __restrict__ attH, __half* __restrict__ attL)
{
    extern __shared__ char smem[];
    const uint32_t sb = smem_to_u32(smem);
    const int tid = threadIdx.x;
    const int lane = tid & 31;
    const int wid = tid >> 5;
    const int wm = wid & 3;
    const int wn = wid >> 2;
    const int b = blockIdx.z;
    const int h = blockIdx.y;
    const int q0 = blockIdx.x * 128;

    float* sMax = (float*)(smem + SM_STAT);
    float* sSum = (float*)(smem + SM_STAT + 1024);

    const size_t rowbase = (size_t)b * SS * N1 + (size_t)h * HD;

    {
        int r = tid >> 1;
        int cbase = (tid & 1) * 6;
        int s = q0 + r;
        int sc_ = s < SS ? s : SS - 1;
        const __half* src = qkv + rowbase + (size_t)sc_ * N1;
#pragma unroll
        for (int cc = 0; cc < 6; ++cc) {
            int c = cbase + cc;
            int ca = c < 11 ? c : 10;
            uint32_t sz = (c < 11 && s < SS) ? 16 : 0;
            cp16(sb + SM_Q + swzQ(r, c), src + ca * 8, sz);
        }
    }

    auto load_kv = [&](int kt, int buf) {
        int r = tid >> 2;
        int cbase = (tid & 3) * 3;
        int s = kt * 64 + r;
        int sc_ = s < SS ? s : SS - 1;
        const uint32_t kb = sb + SM_KV + buf * 24576;
        const __half* baseK = qkv + rowbase + (size_t)sc_ * N1 + DD;
        const __half* baseV = qkv + rowbase + (size_t)sc_ * N1 + 2 * DD;
#pragma unroll
        for (int cc = 0; cc < 3; ++cc) {
            int c = cbase + cc;
            int ca = c < 11 ? c : 10;
            uint32_t sz = (c < 11 && s < SS) ? 16 : 0;
            cp16(kb + swzQ(r, c), baseK + ca * 8, sz);
            cp16(kb + 12288 + swzQ(r, c), baseV + ca * 8, sz);
        }
    };

    load_kv(0, 0);
    CP_COMMIT();

    float acc[2][6][4];
#pragma unroll
    for (int ti = 0; ti < 2; ++ti)
#pragma unroll
        for (int j = 0; j < 6; ++j)
#pragma unroll
            for (int v = 0; v < 4; ++v) acc[ti][j][v] = 0.f;
    float m_old[2][2] = {{-1e30f, -1e30f}, {-1e30f, -1e30f}};
    float l_run[2][2] = {{0.f, 0.f}, {0.f, 0.f}};

    const int NKT = (SS + 63) / 64;

    for (int kt = 0; kt < NKT; ++kt) {
        CP_WAIT(0);
        __syncthreads();
        if (kt + 1 < NKT) load_kv(kt + 1, (kt + 1) & 1);
        CP_COMMIT();

        const uint32_t kb = sb + SM_KV + (kt & 1) * 24576;

        // ---- QK^T ----
        float sc[2][4][4];
#pragma unroll
        for (int ti = 0; ti < 2; ++ti)
#pragma unroll
            for (int j = 0; j < 4; ++j)
#pragma unroll
                for (int v = 0; v < 4; ++v) sc[ti][j][v] = 0.f;

#pragma unroll
        for (int ks = 0; ks < 6; ++ks) {
            uint32_t a[2][4], bq[4][2];
#pragma unroll
            for (int ti = 0; ti < 2; ++ti) {
                int r = wm * 32 + ti * 16 + (lane & 15);
                int c = ks * 2 + (lane >> 4);
                ldsm_x4(a[ti], sb + SM_Q + swzQ(r, c));
            }
#pragma unroll
            for (int j = 0; j < 4; ++j) {
                int r = wn * 32 + j * 8 + (lane & 7);
                int c = ks * 2 + ((lane >> 3) & 1);
                ldsm_x2(bq[j], kb + swzQ(r, c));
            }
#pragma unroll
            for (int ti = 0; ti < 2; ++ti)
#pragma unroll
                for (int j = 0; j < 4; ++j)
                    mma_f32(sc[ti][j], a[ti], bq[j]);
        }

        // ---- mask ----
#pragma unroll
        for (int j = 0; j < 4; ++j) {
            int c0 = kt * 64 + wn * 32 + j * 8 + (lane & 3) * 2;
            if (c0 >= SS) { sc[0][j][0] = sc[0][j][2] = sc[1][j][0] = sc[1][j][2] = -1e30f; }
            if (c0 + 1 >= SS) { sc[0][j][1] = sc[0][j][3] = sc[1][j][1] = sc[1][j][3] = -1e30f; }
        }

        // ---- row max ----
#pragma unroll
        for (int ti = 0; ti < 2; ++ti)
#pragma unroll
            for (int hh = 0; hh < 2; ++hh) {
                float mt = -1e30f;
#pragma unroll
                for (int j = 0; j < 4; ++j)
                    mt = fmaxf(mt, fmaxf(sc[ti][j][hh * 2], sc[ti][j][hh * 2 + 1]));
                mt = fmaxf(mt, __shfl_xor_sync(0xffffffffu, mt, 1));
                mt = fmaxf(mt, __shfl_xor_sync(0xffffffffu, mt, 2));
                if ((lane & 3) == 0) {
                    int rl = wm * 32 + ti * 16 + hh * 8 + (lane >> 2);
                    sMax[wn * 128 + rl] = mt;
                }
            }
        __syncthreads();

        float mnew[2][2], corr[2][2];
#pragma unroll
        for (int ti = 0; ti < 2; ++ti)
#pragma unroll
            for (int hh = 0; hh < 2; ++hh) {
                int rl = wm * 32 + ti * 16 + hh * 8 + (lane >> 2);
                float m2 = fmaxf(sMax[rl], sMax[128 + rl]);
                float mn = fmaxf(m_old[ti][hh], m2);
                corr[ti][hh] = __expf(m_old[ti][hh] - mn);
                mnew[ti][hh] = mn;
                m_old[ti][hh] = mn;
            }

        // ---- exp, P store, sums ----
        float sum_[2][2] = {{0.f, 0.f}, {0.f, 0.f}};
#pragma unroll
        for (int ti = 0; ti < 2; ++ti) {
            int r0 = wm * 32 + ti * 16 + (lane >> 2);
#pragma unroll
            for (int j = 0; j < 4; ++j) {
                float p0 = __expf(sc[ti][j][0] - mnew[ti][0]);
                float p1 = __expf(sc[ti][j][1] - mnew[ti][0]);
                float p2 = __expf(sc[ti][j][2] - mnew[ti][1]);
                float p3 = __expf(sc[ti][j][3] - mnew[ti][1]);
                sum_[ti][0] += p0 + p1;
                sum_[ti][1] += p2 + p3;
                int colc = wn * 32 + j * 8 + (lane & 3) * 2;
                uint32_t o0 = swzP(r0, colc >> 3) + (colc & 7) * 2;
                uint32_t o1 = swzP(r0 + 8, colc >> 3) + (colc & 7) * 2;
                *(uint32_t*)(smem + SM_P + o0) = pack_h2(p0, p1);
                *(uint32_t*)(smem + SM_P + o1) = pack_h2(p2, p3);
            }
        }
#pragma unroll
        for (int ti = 0; ti < 2; ++ti)
#pragma unroll
            for (int hh = 0; hh < 2; ++hh) {
                float s = sum_[ti][hh];
                s += __shfl_xor_sync(0xffffffffu, s, 1);
                s += __shfl_xor_sync(0xffffffffu, s, 2);
                if ((lane & 3) == 0) {
                    int rl = wm * 32 + ti * 16 + hh * 8 + (lane >> 2);
                    sSum[wn * 128 + rl] = s;
                }
            }
#pragma unroll
        for (int ti = 0; ti < 2; ++ti)
#pragma unroll
            for (int j = 0; j < 6; ++j) {
                acc[ti][j][0] *= corr[ti][0];
                acc[ti][j][1] *= corr[ti][0];
                acc[ti][j][2] *= corr[ti][1];
                acc[ti][j][3] *= corr[ti][1];
            }
        __syncthreads();
#pragma unroll
        for (int ti = 0; ti < 2; ++ti)
#pragma unroll
            for (int hh = 0; hh < 2; ++hh) {
                int rl = wm * 32 + ti * 16 + hh * 8 + (lane >> 2);
                l_run[ti][hh] = l_run[ti][hh] * corr[ti][hh] + sSum[rl] + sSum[128 + rl];
            }

        // ---- P.V ----
#pragma unroll
        for (int ks = 0; ks < 4; ++ks) {
            uint32_t p[2][4], v[6][2];
#pragma unroll
            for (int ti = 0; ti < 2; ++ti) {
                int r = wm * 32 + ti * 16 + (lane & 15);
                int c = ks * 2 + (lane >> 4);
                ldsm_x4(p[ti], sb + SM_P + swzP(r, c));
            }
#pragma unroll
            for (int j = 0; j < 6; ++j) {
                int rk = ks * 16 + (lane & 15);
                int c = wn * 6 + j;
                ldsm_x2t(v[j], kb + 12288 + swzQ(rk, c));
            }
#pragma unroll
            for (int ti = 0; ti < 2; ++ti)
#pragma unroll
                for (int j = 0; j < 6; ++j)
                    mma_f32(acc[ti][j], p[ti], v[j]);
        }
    }

    // ---- epilogue ----
    float inv[2][2];
#pragma unroll
    for (int ti = 0; ti < 2; ++ti)
#pragma unroll
        for (int hh = 0; hh < 2; ++hh)
            inv[ti][hh] = 1.f / l_run[ti][hh];

#pragma unroll
    for (int ti = 0; ti < 2; ++ti)
#pragma unroll
        for (int j = 0; j < 6; ++j) {
            int col = wn * 48 + j * 8 + (lane & 3) * 2;
            if (col >= HD) continue;
#pragma unroll
            for (int hh = 0; hh < 2; ++hh) {
                int s = q0 + wm * 32 + ti * 16 + hh * 8 + (lane >> 2);
                if (s >= SS) continue;
                float o0 = acc[ti][j][hh * 2] * inv[ti][hh];
                float o1 = acc[ti][j][hh * 2 + 1] * inv[ti][hh];
                uint32_t hi, lo;
                split_pair(o0, o1, hi, lo);
                size_t off = (size_t)(b * SS + s) * KK + (size_t)h * HD + col;
                *(uint32_t*)&attH[off] = hi;
                *(uint32_t*)&attL[off] = lo;
            }
        }
}

// ---------------------------------------------------------------------------
extern "C" void kernel_launch(void* const* d_in, const int* in_sizes, int n_in,
                              void* d_out, int out_size)
{
    const float* hs     = (const float*)d_in[0];
    const float* w_qkv  = (const float*)d_in[1];
    const float* b_qkv  = (const float*)d_in[2];
    const float* w_proj = (const float*)d_in[3];
    const float* b_proj = (const float*)d_in[4];
    float* out = (float*)d_out;

    __half *hsp, *qkv, *attH, *attL, *wq, *wp;
    cudaGetSymbolAddress((void**)&hsp, g_hs);
    cudaGetSymbolAddress((void**)&qkv, g_qkv);
    cudaGetSymbolAddress((void**)&attH, g_attH);
    cudaGetSymbolAddress((void**)&attL, g_attL);
    cudaGetSymbolAddress((void**)&wq, g_wqkv);
    cudaGetSymbolAddress((void**)&wp, g_wproj);

    const int smem1 = STAGES * 2 * TBYTES;   // 48 KB (1-term)
    const int smem2 = STAGES * 3 * TBYTES;   // 72 KB (2-term)
    cudaFuncSetAttribute((const void*)gemm_mma_kernel<1, 1>,
                         cudaFuncAttributeMaxDynamicSharedMemorySize, smem1);
    cudaFuncSetAttribute((const void*)gemm_mma_kernel<0, 2>,
                         cudaFuncAttributeMaxDynamicSharedMemorySize, smem2);
    cudaFuncSetAttribute((const void*)attn_tc_kernel,
                         cudaFuncAttributeMaxDynamicSharedMemorySize, SM_ATT_TOTAL);

    // 0a) round hidden_states to fp16
    {
        int n4 = MM * KK / 4;
        round_kernel<<<(n4 + 255) / 256, 256>>>((const float4*)hs, (uint2*)hsp, n4);
    }
    // 0b) transpose+round weights to fp16
    {
        dim3 g(N1 / 32, KK / 32);
        ttrunc_kernel<<<g, dim3(32, 8)>>>(w_qkv, wq, KK, N1);
    }
    {
        dim3 g(DD / 32, KK / 32);
        ttrunc_kernel<<<g, dim3(32, 8)>>>(w_proj, wp, KK, DD);
    }
    // 1) QKV projection (1-term) -> single fp16 (q pre-scaled)
    {
        dim3 g(N1 / 128, (MM + 127) / 128);
        gemm_mma_kernel<1, 1><<<g, 256, smem1>>>(hsp, nullptr, wq, b_qkv,
                                                 nullptr, qkv, MM, N1);
    }
    // 2) flash attention (1-term fp16) -> fp16 hi/lo
    {
        dim3 g((SS + 127) / 128, HH, BB);
        attn_tc_kernel<<<g, 256, SM_ATT_TOTAL>>>(qkv, attH, attL);
    }
    // 3) output projection (2-term, error hedge) -> fp32
    {
        dim3 g(DD / 128, (MM + 127) / 128);
        gemm_mma_kernel<0, 2><<<g, 256, smem2>>>(attH, attL, wp, b_proj,
                                                 out, nullptr, MM, DD);
    }
}

// round 11
// speedup vs baseline: 2.3413x; 1.0307x over previous
#include <cuda_runtime.h>
#include <cuda_fp16.h>
#include <cstdint>

// Problem constants
#define BB   16
#define SS   577
#define DD   1408
#define HH   16
#define HD   88
#define SCALE_F 0.10660035817780521f  // 1/sqrt(88)

#define MM   (BB * SS)      // 9232
#define N1   (3 * DD)       // 4224
#define KK   DD             // 1408

// ---------------------------------------------------------------------------
// Device-global scratch (all plain fp16 now)
// ---------------------------------------------------------------------------
__device__ __half g_hs[(size_t)MM * KK];
__device__ __half g_qkv[(size_t)MM * N1];
__device__ __half g_att[(size_t)MM * KK];
__device__ __half g_wqkv[(size_t)N1 * KK];      // transposed [N,K]
__device__ __half g_wproj[(size_t)DD * KK];     // transposed [N,K]

// ---------------------------------------------------------------------------
// PTX helpers (sm_80+ only; harness targets sm_103 w/o 'a' — no tcgen05)
// ---------------------------------------------------------------------------
__device__ __forceinline__ uint32_t smem_to_u32(const void* p) {
    uint32_t a;
    asm("{ .reg .u64 t; cvta.to.shared.u64 t, %1; cvt.u32.u64 %0, t; }"
        : "=r"(a) : "l"(p));
    return a;
}
__device__ __forceinline__ void cp16(uint32_t dst, const void* src, uint32_t sz) {
    asm volatile("cp.async.ca.shared.global [%0], [%1], 16, %2;"
                 :: "r"(dst), "l"(src), "r"(sz) : "memory");
}
#define CP_COMMIT() asm volatile("cp.async.commit_group;" ::: "memory")
#define CP_WAIT(n)  asm volatile("cp.async.wait_group %0;" :: "n"(n) : "memory")

__device__ __forceinline__ void ldsm_x4(uint32_t* r, uint32_t addr) {
    asm volatile("ldmatrix.sync.aligned.m8n8.x4.shared.b16 {%0,%1,%2,%3}, [%4];"
                 : "=r"(r[0]), "=r"(r[1]), "=r"(r[2]), "=r"(r[3]) : "r"(addr));
}
__device__ __forceinline__ void ldsm_x2(uint32_t* r, uint32_t addr) {
    asm volatile("ldmatrix.sync.aligned.m8n8.x2.shared.b16 {%0,%1}, [%2];"
                 : "=r"(r[0]), "=r"(r[1]) : "r"(addr));
}
__device__ __forceinline__ void ldsm_x2t(uint32_t* r, uint32_t addr) {
    asm volatile("ldmatrix.sync.aligned.m8n8.x2.trans.shared.b16 {%0,%1}, [%2];"
                 : "=r"(r[0]), "=r"(r[1]) : "r"(addr));
}
__device__ __forceinline__ void mma_f32(float* d, const uint32_t* a, const uint32_t* b) {
    asm volatile("mma.sync.aligned.m16n8k16.row.col.f32.f16.f16.f32 "
                 "{%0,%1,%2,%3}, {%4,%5,%6,%7}, {%8,%9}, {%0,%1,%2,%3};"
                 : "+f"(d[0]), "+f"(d[1]), "+f"(d[2]), "+f"(d[3])
                 : "r"(a[0]), "r"(a[1]), "r"(a[2]), "r"(a[3]), "r"(b[0]), "r"(b[1]));
}
__device__ __forceinline__ uint32_t pack_h2(float a, float b) {
    __half2 h = __floats2half2_rn(a, b);
    return *reinterpret_cast<uint32_t*>(&h);
}

// ---------------------------------------------------------------------------
// Round fp32 -> fp16, same layout.
// ---------------------------------------------------------------------------
__global__ void round_kernel(const float4* __restrict__ in,
                             uint2* __restrict__ out, int n4)
{
    int i = blockIdx.x * blockDim.x + threadIdx.x;
    if (i >= n4) return;
    float4 v = in[i];
    uint2 o;
    o.x = pack_h2(v.x, v.y);
    o.y = pack_h2(v.z, v.w);
    out[i] = o;
}

// ---------------------------------------------------------------------------
// Transpose + round: in fp32 [R, C] -> fp16 [C, R]
// ---------------------------------------------------------------------------
__global__ void ttrunc_kernel(const float* __restrict__ in,
                              __half* __restrict__ out, int R, int C)
{
    __shared__ float t[32][33];
    int c0 = blockIdx.x * 32, r0 = blockIdx.y * 32;
    int tx = threadIdx.x, ty = threadIdx.y;
#pragma unroll
    for (int i = ty; i < 32; i += 8)
        t[i][tx] = in[(size_t)(r0 + i) * C + c0 + tx];
    __syncthreads();
#pragma unroll
    for (int i = ty; i < 32; i += 8)
        out[(size_t)(c0 + i) * R + r0 + tx] = __float2half_rn(t[tx][i]);
}

// ---------------------------------------------------------------------------
// fp16 MMA GEMM: C[M,N] = A[M,K] @ B[N,K]^T + bias[N]
// CTA tile 256x128, warp tile 64x64 (8 warps = 4M x 2N), BK=32, 3 stages
// (72 KB). LDSM/MMA wavefront ratio 1.0.
// MODE 0: fp32 C out.  MODE 1: single fp16 out, cols<DD scaled by SCALE_F.
// ---------------------------------------------------------------------------
#define BK      32
#define STAGES  3
#define ATILE   16384            // 256 rows * 64 B
#define BTILE   8192             // 128 rows * 64 B
#define STG_BYTES (ATILE + BTILE)
#define NCH     (KK / BK)

__device__ __forceinline__ uint32_t swz(int r, int c) {
    return (uint32_t)(r * 64 + ((c ^ ((r >> 1) & 3)) << 4));
}

template<int MODE>
__global__ __launch_bounds__(256, 1) void gemm_mma_kernel(
    const __half* __restrict__ A, const __half* __restrict__ B,
    const float* __restrict__ bias, float* __restrict__ C,
    __half* __restrict__ CH, int M, int N)
{
    extern __shared__ char smem[];
    const uint32_t sbase = smem_to_u32(smem);

    const int tid = threadIdx.x;
    const int lane = tid & 31;
    const int wid = tid >> 5;
    const int wm = wid & 3;          // 4 warps along M (64 rows each)
    const int wn = wid >> 2;         // 2 warps along N (64 cols each)
    const int m0 = blockIdx.y * 256;
    const int n0 = blockIdx.x * 128;

    // stage loader: 1536 16B-chunks, 6 per thread
    auto load_stage = [&](int kt, int slot) {
        const int k0 = kt * BK;
        const uint32_t st = sbase + slot * STG_BYTES;
#pragma unroll
        for (int i = 0; i < 6; ++i) {
            int idx = tid + i * 256;
            const __half* gp;
            uint32_t dst;
            uint32_t sz = 16;
            if (idx < 1024) {                  // A: 256 rows x 4 chunks
                int r = idx >> 2;
                int c = idx & 3;
                int m = m0 + r;
                int mc = m < M ? m : 0;
                if (m >= M) sz = 0;
                gp = A + (size_t)mc * KK + k0 + c * 8;
                dst = st + swz(r, c);
            } else {                           // B: 128 rows x 4 chunks
                int idx2 = idx - 1024;
                int r = idx2 >> 2;
                int c = idx2 & 3;
                int n = n0 + r;
                gp = B + (size_t)n * KK + k0 + c * 8;
                dst = st + ATILE + swz(r, c);
            }
            cp16(dst, gp, sz);
        }
        CP_COMMIT();
    };

    float acc[4][8][4];
#pragma unroll
    for (int t = 0; t < 4; ++t)
#pragma unroll
        for (int j = 0; j < 8; ++j)
#pragma unroll
            for (int v = 0; v < 4; ++v) acc[t][j][v] = 0.f;

    load_stage(0, 0);
    load_stage(1, 1);

    const int arow = wm * 64 + (lane & 15);
    const int acl = lane >> 4;
    const int brow = wn * 64 + (lane & 7) + ((lane >> 4) & 1) * 8;
    const int bcl = (lane >> 3) & 1;

    for (int kt = 0; kt < NCH; ++kt) {
        CP_WAIT(1);
        __syncthreads();
        if (kt + 2 < NCH) load_stage(kt + 2, (kt + 2) % STAGES);

        const uint32_t st = sbase + (kt % STAGES) * STG_BYTES;
#pragma unroll
        for (int ks = 0; ks < 2; ++ks) {
            uint32_t a[4][4], b[4][4];
#pragma unroll
            for (int t = 0; t < 4; ++t)
                ldsm_x4(a[t], st + swz(arow + t * 16, ks * 2 + acl));
#pragma unroll
            for (int jj = 0; jj < 4; ++jj)
                ldsm_x4(b[jj], st + ATILE + swz(brow + jj * 16, ks * 2 + bcl));
#pragma unroll
            for (int t = 0; t < 4; ++t)
#pragma unroll
                for (int jj = 0; jj < 4; ++jj) {
                    mma_f32(acc[t][jj * 2 + 0], a[t], &b[jj][0]);
                    mma_f32(acc[t][jj * 2 + 1], a[t], &b[jj][2]);
                }
        }
    }

    const int rb = m0 + wm * 64 + (lane >> 2);
    const int cb = n0 + wn * 64 + (lane & 3) * 2;
#pragma unroll
    for (int t = 0; t < 4; ++t) {
        int r0 = rb + t * 16;
#pragma unroll
        for (int j = 0; j < 8; ++j) {
            int col = cb + j * 8;
            float2 b2 = *(const float2*)&bias[col];
            if constexpr (MODE == 0) {
                if (r0 < M) {
                    float2 o = {acc[t][j][0] + b2.x, acc[t][j][1] + b2.y};
                    *(float2*)&C[(size_t)r0 * N + col] = o;
                }
                if (r0 + 8 < M) {
                    float2 o = {acc[t][j][2] + b2.x, acc[t][j][3] + b2.y};
                    *(float2*)&C[(size_t)(r0 + 8) * N + col] = o;
                }
            } else {
                float s = (col < DD) ? SCALE_F : 1.0f;
                if (r0 < M)
                    *(uint32_t*)&CH[(size_t)r0 * N + col] =
                        pack_h2((acc[t][j][0] + b2.x) * s, (acc[t][j][1] + b2.y) * s);
                if (r0 + 8 < M)
                    *(uint32_t*)&CH[(size_t)(r0 + 8) * N + col] =
                        pack_h2((acc[t][j][2] + b2.x) * s, (acc[t][j][3] + b2.y) * s);
            }
        }
    }
}

// ---------------------------------------------------------------------------
// Tensor-core flash attention, plain fp16 (1 MMA per product, fp32 accum).
// smem: Q 24KB | KV 2x24KB | P 16KB | stats 2KB = 90KB -> 2 CTAs/SM.
// Epilogue writes plain fp16 att (GEMM2 is 1-term now).
// ---------------------------------------------------------------------------
#define SM_Q    0
#define SM_KV   24576            // buf stride 24576: K@0, V@12288
#define SM_P    73728
#define SM_STAT 90112
#define SM_ATT_TOTAL 92160

__device__ __forceinline__ uint32_t swzQ(int r, int c) {
    return (uint32_t)(r * 192 + ((c ^ ((r >> 1) & 3)) << 4));
}
__device__ __forceinline__ uint32_t swzP(int r, int c) {
    return (uint32_t)(r * 128 + ((c ^ (r & 7)) << 4));
}

__global__ __launch_bounds__(256, 2) void attn_tc_kernel(
    const __half* __restrict__ qkv, __half* __restrict__ att)
{
    extern __shared__ char smem[];
    const uint32_t sb = smem_to_u32(smem);
    const int tid = threadIdx.x;
    const int lane = tid & 31;
    const int wid = tid >> 5;
    const int wm = wid & 3;
    const int wn = wid >> 2;
    const int b = blockIdx.z;
    const int h = blockIdx.y;
    const int q0 = blockIdx.x * 128;

    float* sMax = (float*)(smem + SM_STAT);
    float* sSum = (float*)(smem + SM_STAT + 1024);

    const size_t rowbase = (size_t)b * SS * N1 + (size_t)h * HD;

    {
        int r = tid >> 1;
        int cbase = (tid & 1) * 6;
        int s = q0 + r;
        int sc_ = s < SS ? s : SS - 1;
        const __half* src = qkv + rowbase + (size_t)sc_ * N1;
#pragma unroll
        for (int cc = 0; cc < 6; ++cc) {
            int c = cbase + cc;
            int ca = c < 11 ? c : 10;
            uint32_t sz = (c < 11 && s < SS) ? 16 : 0;
            cp16(sb + SM_Q + swzQ(r, c), src + ca * 8, sz);
        }
    }

    auto load_kv = [&](int kt, int buf) {
        int r = tid >> 2;
        int cbase = (tid & 3) * 3;
        int s = kt * 64 + r;
        int sc_ = s < SS ? s : SS - 1;
        const uint32_t kb = sb + SM_KV + buf * 24576;
        const __half* baseK = qkv + rowbase + (size_t)sc_ * N1 + DD;
        const __half* baseV = qkv + rowbase + (size_t)sc_ * N1 + 2 * DD;
#pragma unroll
        for (int cc = 0; cc < 3; ++cc) {
            int c = cbase + cc;
            int ca = c < 11 ? c : 10;
            uint32_t sz = (c < 11 && s < SS) ? 16 : 0;
            cp16(kb + swzQ(r, c), baseK + ca * 8, sz);
            cp16(kb + 12288 + swzQ(r, c), baseV + ca * 8, sz);
        }
    };

    load_kv(0, 0);
    CP_COMMIT();

    float acc[2][6][4];
#pragma unroll
    for (int ti = 0; ti < 2; ++ti)
#pragma unroll
        for (int j = 0; j < 6; ++j)
#pragma unroll
            for (int v = 0; v < 4; ++v) acc[ti][j][v] = 0.f;
    float m_old[2][2] = {{-1e30f, -1e30f}, {-1e30f, -1e30f}};
    float l_run[2][2] = {{0.f, 0.f}, {0.f, 0.f}};

    const int NKT = (SS + 63) / 64;

    for (int kt = 0; kt < NKT; ++kt) {
        CP_WAIT(0);
        __syncthreads();
        if (kt + 1 < NKT) load_kv(kt + 1, (kt + 1) & 1);
        CP_COMMIT();

        const uint32_t kb = sb + SM_KV + (kt & 1) * 24576;

        // ---- QK^T ----
        float sc[2][4][4];
#pragma unroll
        for (int ti = 0; ti < 2; ++ti)
#pragma unroll
            for (int j = 0; j < 4; ++j)
#pragma unroll
                for (int v = 0; v < 4; ++v) sc[ti][j][v] = 0.f;

#pragma unroll
        for (int ks = 0; ks < 6; ++ks) {
            uint32_t a[2][4], bq[4][2];
#pragma unroll
            for (int ti = 0; ti < 2; ++ti) {
                int r = wm * 32 + ti * 16 + (lane & 15);
                int c = ks * 2 + (lane >> 4);
                ldsm_x4(a[ti], sb + SM_Q + swzQ(r, c));
            }
#pragma unroll
            for (int j = 0; j < 4; ++j) {
                int r = wn * 32 + j * 8 + (lane & 7);
                int c = ks * 2 + ((lane >> 3) & 1);
                ldsm_x2(bq[j], kb + swzQ(r, c));
            }
#pragma unroll
            for (int ti = 0; ti < 2; ++ti)
#pragma unroll
                for (int j = 0; j < 4; ++j)
                    mma_f32(sc[ti][j], a[ti], bq[j]);
        }

        // ---- mask ----
#pragma unroll
        for (int j = 0; j < 4; ++j) {
            int c0 = kt * 64 + wn * 32 + j * 8 + (lane & 3) * 2;
            if (c0 >= SS) { sc[0][j][0] = sc[0][j][2] = sc[1][j][0] = sc[1][j][2] = -1e30f; }
            if (c0 + 1 >= SS) { sc[0][j][1] = sc[0][j][3] = sc[1][j][1] = sc[1][j][3] = -1e30f; }
        }

        // ---- row max ----
#pragma unroll
        for (int ti = 0; ti < 2; ++ti)
#pragma unroll
            for (int hh = 0; hh < 2; ++hh) {
                float mt = -1e30f;
#pragma unroll
                for (int j = 0; j < 4; ++j)
                    mt = fmaxf(mt, fmaxf(sc[ti][j][hh * 2], sc[ti][j][hh * 2 + 1]));
                mt = fmaxf(mt, __shfl_xor_sync(0xffffffffu, mt, 1));
                mt = fmaxf(mt, __shfl_xor_sync(0xffffffffu, mt, 2));
                if ((lane & 3) == 0) {
                    int rl = wm * 32 + ti * 16 + hh * 8 + (lane >> 2);
                    sMax[wn * 128 + rl] = mt;
                }
            }
        __syncthreads();

        float mnew[2][2], corr[2][2];
#pragma unroll
        for (int ti = 0; ti < 2; ++ti)
#pragma unroll
            for (int hh = 0; hh < 2; ++hh) {
                int rl = wm * 32 + ti * 16 + hh * 8 + (lane >> 2);
                float m2 = fmaxf(sMax[rl], sMax[128 + rl]);
                float mn = fmaxf(m_old[ti][hh], m2);
                corr[ti][hh] = __expf(m_old[ti][hh] - mn);
                mnew[ti][hh] = mn;
                m_old[ti][hh] = mn;
            }

        // ---- exp, P store, sums ----
        float sum_[2][2] = {{0.f, 0.f}, {0.f, 0.f}};
#pragma unroll
        for (int ti = 0; ti < 2; ++ti) {
            int r0 = wm * 32 + ti * 16 + (lane >> 2);
#pragma unroll
            for (int j = 0; j < 4; ++j) {
                float p0 = __expf(sc[ti][j][0] - mnew[ti][0]);
                float p1 = __expf(sc[ti][j][1] - mnew[ti][0]);
                float p2 = __expf(sc[ti][j][2] - mnew[ti][1]);
                float p3 = __expf(sc[ti][j][3] - mnew[ti][1]);
                sum_[ti][0] += p0 + p1;
                sum_[ti][1] += p2 + p3;
                int colc = wn * 32 + j * 8 + (lane & 3) * 2;
                uint32_t o0 = swzP(r0, colc >> 3) + (colc & 7) * 2;
                uint32_t o1 = swzP(r0 + 8, colc >> 3) + (colc & 7) * 2;
                *(uint32_t*)(smem + SM_P + o0) = pack_h2(p0, p1);
                *(uint32_t*)(smem + SM_P + o1) = pack_h2(p2, p3);
            }
        }
#pragma unroll
        for (int ti = 0; ti < 2; ++ti)
#pragma unroll
            for (int hh = 0; hh < 2; ++hh) {
                float s = sum_[ti][hh];
                s += __shfl_xor_sync(0xffffffffu, s, 1);
                s += __shfl_xor_sync(0xffffffffu, s, 2);
                if ((lane & 3) == 0) {
                    int rl = wm * 32 + ti * 16 + hh * 8 + (lane >> 2);
                    sSum[wn * 128 + rl] = s;
                }
            }
#pragma unroll
        for (int ti = 0; ti < 2; ++ti)
#pragma unroll
            for (int j = 0; j < 6; ++j) {
                acc[ti][j][0] *= corr[ti][0];
                acc[ti][j][1] *= corr[ti][0];
                acc[ti][j][2] *= corr[ti][1];
                acc[ti][j][3] *= corr[ti][1];
            }
        __syncthreads();
#pragma unroll
        for (int ti = 0; ti < 2; ++ti)
#pragma unroll
            for (int hh = 0; hh < 2; ++hh) {
                int rl = wm * 32 + ti * 16 + hh * 8 + (lane >> 2);
                l_run[ti][hh] = l_run[ti][hh] * corr[ti][hh] + sSum[rl] + sSum[128 + rl];
            }

        // ---- P.V ----
#pragma unroll
        for (int ks = 0; ks < 4; ++ks) {
            uint32_t p[2][4], v[6][2];
#pragma unroll
            for (int ti = 0; ti < 2; ++ti) {
                int r = wm * 32 + ti * 16 + (lane & 15);
                int c = ks * 2 + (lane >> 4);
                ldsm_x4(p[ti], sb + SM_P + swzP(r, c));
            }
#pragma unroll
            for (int j = 0; j < 6; ++j) {
                int rk = ks * 16 + (lane & 15);
                int c = wn * 6 + j;
                ldsm_x2t(v[j], kb + 12288 + swzQ(rk, c));
            }
#pragma unroll
            for (int ti = 0; ti < 2; ++ti)
#pragma unroll
                for (int j = 0; j < 6; ++j)
                    mma_f32(acc[ti][j], p[ti], v[j]);
        }
    }

    // ---- epilogue: normalize, round to fp16, store ----
    float inv[2][2];
#pragma unroll
    for (int ti = 0; ti < 2; ++ti)
#pragma unroll
        for (int hh = 0; hh < 2; ++hh)
            inv[ti][hh] = 1.f / l_run[ti][hh];

#pragma unroll
    for (int ti = 0; ti < 2; ++ti)
#pragma unroll
        for (int j = 0; j < 6; ++j) {
            int col = wn * 48 + j * 8 + (lane & 3) * 2;
            if (col >= HD) continue;
#pragma unroll
            for (int hh = 0; hh < 2; ++hh) {
                int s = q0 + wm * 32 + ti * 16 + hh * 8 + (lane >> 2);
                if (s >= SS) continue;
                float o0 = acc[ti][j][hh * 2] * inv[ti][hh];
                float o1 = acc[ti][j][hh * 2 + 1] * inv[ti][hh];
                size_t off = (size_t)(b * SS + s) * KK + (size_t)h * HD + col;
                *(uint32_t*)&att[off] = pack_h2(o0, o1);
            }
        }
}

// ---------------------------------------------------------------------------
extern "C" void kernel_launch(void* const* d_in, const int* in_sizes, int n_in,
                              void* d_out, int out_size)
{
    const float* hs     = (const float*)d_in[0];
    const float* w_qkv  = (const float*)d_in[1];
    const float* b_qkv  = (const float*)d_in[2];
    const float* w_proj = (const float*)d_in[3];
    const float* b_proj = (const float*)d_in[4];
    float* out = (float*)d_out;

    __half *hsp, *qkv, *att, *wq, *wp;
    cudaGetSymbolAddress((void**)&hsp, g_hs);
    cudaGetSymbolAddress((void**)&qkv, g_qkv);
    cudaGetSymbolAddress((void**)&att, g_att);
    cudaGetSymbolAddress((void**)&wq, g_wqkv);
    cudaGetSymbolAddress((void**)&wp, g_wproj);

    const int gemm_smem = STAGES * STG_BYTES;   // 72 KB
    cudaFuncSetAttribute((const void*)gemm_mma_kernel<0>,
                         cudaFuncAttributeMaxDynamicSharedMemorySize, gemm_smem);
    cudaFuncSetAttribute((const void*)gemm_mma_kernel<1>,
                         cudaFuncAttributeMaxDynamicSharedMemorySize, gemm_smem);
    cudaFuncSetAttribute((const void*)attn_tc_kernel,
                         cudaFuncAttributeMaxDynamicSharedMemorySize, SM_ATT_TOTAL);

    // 0a) round hidden_states to fp16
    {
        int n4 = MM * KK / 4;
        round_kernel<<<(n4 + 255) / 256, 256>>>((const float4*)hs, (uint2*)hsp, n4);
    }
    // 0b) transpose+round weights to fp16
    {
        dim3 g(N1 / 32, KK / 32);
        ttrunc_kernel<<<g, dim3(32, 8)>>>(w_qkv, wq, KK, N1);
    }
    {
        dim3 g(DD / 32, KK / 32);
        ttrunc_kernel<<<g, dim3(32, 8)>>>(w_proj, wp, KK, DD);
    }
    // 1) QKV projection -> single fp16 (q pre-scaled)
    {
        dim3 g(N1 / 128, (MM + 255) / 256);
        gemm_mma_kernel<1><<<g, 256, gemm_smem>>>(hsp, wq, b_qkv,
                                                  nullptr, qkv, MM, N1);
    }
    // 2) flash attention (fp16) -> plain fp16
    {
        dim3 g((SS + 127) / 128, HH, BB);
        attn_tc_kernel<<<g, 256, SM_ATT_TOTAL>>>(qkv, att);
    }
    // 3) output projection -> fp32
    {
        dim3 g(DD / 128, (MM + 255) / 256);
        gemm_mma_kernel<0><<<g, 256, gemm_smem>>>(att, wp, b_proj,
                                                  out, nullptr, MM, DD);
    }
}

// round 12
// speedup vs baseline: 2.5628x; 1.0946x over previous
#include <cuda_runtime.h>
#include <cuda_fp16.h>
#include <cstdint>

// Problem constants
#define BB   16
#define SS   577
#define DD   1408
#define HH   16
#define HD   88
#define SCALE_F 0.10660035817780521f  // 1/sqrt(88)

#define MM   (BB * SS)      // 9232
#define N1   (3 * DD)       // 4224
#define KK   DD             // 1408

// ---------------------------------------------------------------------------
// Device-global scratch (all plain fp16)
// ---------------------------------------------------------------------------
__device__ __half g_hs[(size_t)MM * KK];
__device__ __half g_qkv[(size_t)MM * N1];
__device__ __half g_att[(size_t)MM * KK];
__device__ __half g_wqkv[(size_t)N1 * KK];      // transposed [N,K]
__device__ __half g_wproj[(size_t)DD * KK];     // transposed [N,K]

// ---------------------------------------------------------------------------
// PTX helpers (sm_80+ only; harness targets sm_103 w/o 'a' — no tcgen05)
// ---------------------------------------------------------------------------
__device__ __forceinline__ uint32_t smem_to_u32(const void* p) {
    uint32_t a;
    asm("{ .reg .u64 t; cvta.to.shared.u64 t, %1; cvt.u32.u64 %0, t; }"
        : "=r"(a) : "l"(p));
    return a;
}
__device__ __forceinline__ void cp16(uint32_t dst, const void* src, uint32_t sz) {
    asm volatile("cp.async.ca.shared.global [%0], [%1], 16, %2;"
                 :: "r"(dst), "l"(src), "r"(sz) : "memory");
}
#define CP_COMMIT() asm volatile("cp.async.commit_group;" ::: "memory")
#define CP_WAIT(n)  asm volatile("cp.async.wait_group %0;" :: "n"(n) : "memory")

__device__ __forceinline__ void ldsm_x4(uint32_t* r, uint32_t addr) {
    asm volatile("ldmatrix.sync.aligned.m8n8.x4.shared.b16 {%0,%1,%2,%3}, [%4];"
                 : "=r"(r[0]), "=r"(r[1]), "=r"(r[2]), "=r"(r[3]) : "r"(addr));
}
__device__ __forceinline__ void ldsm_x2(uint32_t* r, uint32_t addr) {
    asm volatile("ldmatrix.sync.aligned.m8n8.x2.shared.b16 {%0,%1}, [%2];"
                 : "=r"(r[0]), "=r"(r[1]) : "r"(addr));
}
__device__ __forceinline__ void ldsm_x2t(uint32_t* r, uint32_t addr) {
    asm volatile("ldmatrix.sync.aligned.m8n8.x2.trans.shared.b16 {%0,%1}, [%2];"
                 : "=r"(r[0]), "=r"(r[1]) : "r"(addr));
}
__device__ __forceinline__ void mma_f32(float* d, const uint32_t* a, const uint32_t* b) {
    asm volatile("mma.sync.aligned.m16n8k16.row.col.f32.f16.f16.f32 "
                 "{%0,%1,%2,%3}, {%4,%5,%6,%7}, {%8,%9}, {%0,%1,%2,%3};"
                 : "+f"(d[0]), "+f"(d[1]), "+f"(d[2]), "+f"(d[3])
                 : "r"(a[0]), "r"(a[1]), "r"(a[2]), "r"(a[3]), "r"(b[0]), "r"(b[1]));
}
__device__ __forceinline__ uint32_t pack_h2(float a, float b) {
    __half2 h = __floats2half2_rn(a, b);
    return *reinterpret_cast<uint32_t*>(&h);
}

// ---------------------------------------------------------------------------
// Round fp32 -> fp16, same layout.
// ---------------------------------------------------------------------------
__global__ void round_kernel(const float4* __restrict__ in,
                             uint2* __restrict__ out, int n4)
{
    int i = blockIdx.x * blockDim.x + threadIdx.x;
    if (i >= n4) return;
    float4 v = in[i];
    uint2 o;
    o.x = pack_h2(v.x, v.y);
    o.y = pack_h2(v.z, v.w);
    out[i] = o;
}

// ---------------------------------------------------------------------------
// Transpose + round: in fp32 [R, C] -> fp16 [C, R]
// ---------------------------------------------------------------------------
__global__ void ttrunc_kernel(const float* __restrict__ in,
                              __half* __restrict__ out, int R, int C)
{
    __shared__ float t[32][33];
    int c0 = blockIdx.x * 32, r0 = blockIdx.y * 32;
    int tx = threadIdx.x, ty = threadIdx.y;
#pragma unroll
    for (int i = ty; i < 32; i += 8)
        t[i][tx] = in[(size_t)(r0 + i) * C + c0 + tx];
    __syncthreads();
#pragma unroll
    for (int i = ty; i < 32; i += 8)
        out[(size_t)(c0 + i) * R + r0 + tx] = __float2half_rn(t[tx][i]);
}

// ---------------------------------------------------------------------------
// fp16 MMA GEMM: C[M,N] = A[M,K] @ B[N,K]^T + bias[N]
// R10 geometry (best measured): CTA 128x128, warp tile 32x64 (8 warps
// 4M x 2N), BK=32, 3 stages (48 KB), 2 CTAs/SM.
// MODE 0: fp32 C out.  MODE 1: single fp16 out, cols<DD scaled by SCALE_F.
// ---------------------------------------------------------------------------
#define BK      32
#define STAGES  3
#define TBYTES  8192
#define STG_BYTES (2 * TBYTES)   // A | B
#define NCH     (KK / BK)

__device__ __forceinline__ uint32_t swz(int r, int c) {
    return (uint32_t)(r * 64 + ((c ^ ((r >> 1) & 3)) << 4));
}

template<int MODE>
__global__ __launch_bounds__(256, 2) void gemm_mma_kernel(
    const __half* __restrict__ A, const __half* __restrict__ B,
    const float* __restrict__ bias, float* __restrict__ C,
    __half* __restrict__ CH, int M, int N)
{
    extern __shared__ char smem[];
    const uint32_t sbase = smem_to_u32(smem);

    const int tid = threadIdx.x;
    const int lane = tid & 31;
    const int wid = tid >> 5;
    const int wm = wid & 3;
    const int wn = wid >> 2;
    const int m0 = blockIdx.y * 128;
    const int n0 = blockIdx.x * 128;

    auto load_stage = [&](int kt, int slot) {
        const int k0 = kt * BK;
        const uint32_t st = sbase + slot * STG_BYTES;
#pragma unroll
        for (int i = 0; i < 4; ++i) {
            int idx = tid + i * 256;       // 0..1023
            int tile = idx >> 9;           // 0: A, 1: B
            int rem = idx & 511;
            int r = rem >> 2;
            int c = rem & 3;
            uint32_t dst = st + tile * TBYTES + swz(r, c);
            const __half* gp;
            uint32_t sz = 16;
            if (tile == 0) {
                int m = m0 + r;
                int mc = m < M ? m : 0;
                if (m >= M) sz = 0;
                gp = A + (size_t)mc * KK + k0 + c * 8;
            } else {
                int n = n0 + r;
                gp = B + (size_t)n * KK + k0 + c * 8;
            }
            cp16(dst, gp, sz);
        }
        CP_COMMIT();
    };

    float acc[2][8][4];
#pragma unroll
    for (int t = 0; t < 2; ++t)
#pragma unroll
        for (int j = 0; j < 8; ++j)
#pragma unroll
            for (int v = 0; v < 4; ++v) acc[t][j][v] = 0.f;

    load_stage(0, 0);
    load_stage(1, 1);

    const int ar[2] = { wm * 32 + (lane & 15), wm * 32 + 16 + (lane & 15) };
    const int acl = (lane >> 4);
    const int br = wn * 64 + (lane & 7) + ((lane >> 4) & 1) * 8;
    const int bcl = (lane >> 3) & 1;

    for (int kt = 0; kt < NCH; ++kt) {
        CP_WAIT(1);
        __syncthreads();
        if (kt + 2 < NCH) load_stage(kt + 2, (kt + 2) % STAGES);

        const uint32_t st = sbase + (kt % STAGES) * STG_BYTES;
#pragma unroll
        for (int ks = 0; ks < 2; ++ks) {
            uint32_t a[2][4], b[4][4];
#pragma unroll
            for (int t = 0; t < 2; ++t)
                ldsm_x4(a[t], st + swz(ar[t], ks * 2 + acl));
#pragma unroll
            for (int jj = 0; jj < 4; ++jj)
                ldsm_x4(b[jj], st + TBYTES + swz(br + jj * 16, ks * 2 + bcl));
#pragma unroll
            for (int t = 0; t < 2; ++t)
#pragma unroll
                for (int jj = 0; jj < 4; ++jj) {
                    mma_f32(acc[t][jj * 2 + 0], a[t], &b[jj][0]);
                    mma_f32(acc[t][jj * 2 + 1], a[t], &b[jj][2]);
                }
        }
    }

    const int rb = m0 + wm * 32 + (lane >> 2);
    const int cb = n0 + wn * 64 + (lane & 3) * 2;
#pragma unroll
    for (int t = 0; t < 2; ++t) {
        int r0 = rb + t * 16;
#pragma unroll
        for (int j = 0; j < 8; ++j) {
            int col = cb + j * 8;
            float2 b2 = *(const float2*)&bias[col];
            if constexpr (MODE == 0) {
                if (r0 < M) {
                    float2 o = {acc[t][j][0] + b2.x, acc[t][j][1] + b2.y};
                    *(float2*)&C[(size_t)r0 * N + col] = o;
                }
                if (r0 + 8 < M) {
                    float2 o = {acc[t][j][2] + b2.x, acc[t][j][3] + b2.y};
                    *(float2*)&C[(size_t)(r0 + 8) * N + col] = o;
                }
            } else {
                float s = (col < DD) ? SCALE_F : 1.0f;
                if (r0 < M)
                    *(uint32_t*)&CH[(size_t)r0 * N + col] =
                        pack_h2((acc[t][j][0] + b2.x) * s, (acc[t][j][1] + b2.y) * s);
                if (r0 + 8 < M)
                    *(uint32_t*)&CH[(size_t)(r0 + 8) * N + col] =
                        pack_h2((acc[t][j][2] + b2.x) * s, (acc[t][j][3] + b2.y) * s);
            }
        }
    }
}

// ---------------------------------------------------------------------------
// Tensor-core flash attention, plain fp16 (1 MMA per product, fp32 accum).
// smem: Q 24KB | KV 2x24KB | P 16KB | stats 2KB = 90KB -> 2 CTAs/SM.
// ---------------------------------------------------------------------------
#define SM_Q    0
#define SM_KV   24576            // buf stride 24576: K@0, V@12288
#define SM_P    73728
#define SM_STAT 90112
#define SM_ATT_TOTAL 92160

__device__ __forceinline__ uint32_t swzQ(int r, int c) {
    return (uint32_t)(r * 192 + ((c ^ ((r >> 1) & 3)) << 4));
}
__device__ __forceinline__ uint32_t swzP(int r, int c) {
    return (uint32_t)(r * 128 + ((c ^ (r & 7)) << 4));
}

__global__ __launch_bounds__(256, 2) void attn_tc_kernel(
    const __half* __restrict__ qkv, __half* __restrict__ att)
{
    extern __shared__ char smem[];
    const uint32_t sb = smem_to_u32(smem);
    const int tid = threadIdx.x;
    const int lane = tid & 31;
    const int wid = tid >> 5;
    const int wm = wid & 3;
    const int wn = wid >> 2;
    const int b = blockIdx.z;
    const int h = blockIdx.y;
    const int q0 = blockIdx.x * 128;

    float* sMax = (float*)(smem + SM_STAT);
    float* sSum = (float*)(smem + SM_STAT + 1024);

    const size_t rowbase = (size_t)b * SS * N1 + (size_t)h * HD;

    {
        int r = tid >> 1;
        int cbase = (tid & 1) * 6;
        int s = q0 + r;
        int sc_ = s < SS ? s : SS - 1;
        const __half* src = qkv + rowbase + (size_t)sc_ * N1;
#pragma unroll
        for (int cc = 0; cc < 6; ++cc) {
            int c = cbase + cc;
            int ca = c < 11 ? c : 10;
            uint32_t sz = (c < 11 && s < SS) ? 16 : 0;
            cp16(sb + SM_Q + swzQ(r, c), src + ca * 8, sz);
        }
    }

    auto load_kv = [&](int kt, int buf) {
        int r = tid >> 2;
        int cbase = (tid & 3) * 3;
        int s = kt * 64 + r;
        int sc_ = s < SS ? s : SS - 1;
        const uint32_t kb = sb + SM_KV + buf * 24576;
        const __half* baseK = qkv + rowbase + (size_t)sc_ * N1 + DD;
        const __half* baseV = qkv + rowbase + (size_t)sc_ * N1 + 2 * DD;
#pragma unroll
        for (int cc = 0; cc < 3; ++cc) {
            int c = cbase + cc;
            int ca = c < 11 ? c : 10;
            uint32_t sz = (c < 11 && s < SS) ? 16 : 0;
            cp16(kb + swzQ(r, c), baseK + ca * 8, sz);
            cp16(kb + 12288 + swzQ(r, c), baseV + ca * 8, sz);
        }
    };

    load_kv(0, 0);
    CP_COMMIT();

    float acc[2][6][4];
#pragma unroll
    for (int ti = 0; ti < 2; ++ti)
#pragma unroll
        for (int j = 0; j < 6; ++j)
#pragma unroll
            for (int v = 0; v < 4; ++v) acc[ti][j][v] = 0.f;
    float m_old[2][2] = {{-1e30f, -1e30f}, {-1e30f, -1e30f}};
    float l_run[2][2] = {{0.f, 0.f}, {0.f, 0.f}};

    const int NKT = (SS + 63) / 64;

    for (int kt = 0; kt < NKT; ++kt) {
        CP_WAIT(0);
        __syncthreads();
        if (kt + 1 < NKT) load_kv(kt + 1, (kt + 1) & 1);
        CP_COMMIT();

        const uint32_t kb = sb + SM_KV + (kt & 1) * 24576;

        // ---- QK^T ----
        float sc[2][4][4];
#pragma unroll
        for (int ti = 0; ti < 2; ++ti)
#pragma unroll
            for (int j = 0; j < 4; ++j)
#pragma unroll
                for (int v = 0; v < 4; ++v) sc[ti][j][v] = 0.f;

#pragma unroll
        for (int ks = 0; ks < 6; ++ks) {
            uint32_t a[2][4], bq[4][2];
#pragma unroll
            for (int ti = 0; ti < 2; ++ti) {
                int r = wm * 32 + ti * 16 + (lane & 15);
                int c = ks * 2 + (lane >> 4);
                ldsm_x4(a[ti], sb + SM_Q + swzQ(r, c));
            }
#pragma unroll
            for (int j = 0; j < 4; ++j) {
                int r = wn * 32 + j * 8 + (lane & 7);
                int c = ks * 2 + ((lane >> 3) & 1);
                ldsm_x2(bq[j], kb + swzQ(r, c));
            }
#pragma unroll
            for (int ti = 0; ti < 2; ++ti)
#pragma unroll
                for (int j = 0; j < 4; ++j)
                    mma_f32(sc[ti][j], a[ti], bq[j]);
        }

        // ---- mask ----
#pragma unroll
        for (int j = 0; j < 4; ++j) {
            int c0 = kt * 64 + wn * 32 + j * 8 + (lane & 3) * 2;
            if (c0 >= SS) { sc[0][j][0] = sc[0][j][2] = sc[1][j][0] = sc[1][j][2] = -1e30f; }
            if (c0 + 1 >= SS) { sc[0][j][1] = sc[0][j][3] = sc[1][j][1] = sc[1][j][3] = -1e30f; }
        }

        // ---- row max ----
#pragma unroll
        for (int ti = 0; ti < 2; ++ti)
#pragma unroll
            for (int hh = 0; hh < 2; ++hh) {
                float mt = -1e30f;
#pragma unroll
                for (int j = 0; j < 4; ++j)
                    mt = fmaxf(mt, fmaxf(sc[ti][j][hh * 2], sc[ti][j][hh * 2 + 1]));
                mt = fmaxf(mt, __shfl_xor_sync(0xffffffffu, mt, 1));
                mt = fmaxf(mt, __shfl_xor_sync(0xffffffffu, mt, 2));
                if ((lane & 3) == 0) {
                    int rl = wm * 32 + ti * 16 + hh * 8 + (lane >> 2);
                    sMax[wn * 128 + rl] = mt;
                }
            }
        __syncthreads();

        float mnew[2][2], corr[2][2];
#pragma unroll
        for (int ti = 0; ti < 2; ++ti)
#pragma unroll
            for (int hh = 0; hh < 2; ++hh) {
                int rl = wm * 32 + ti * 16 + hh * 8 + (lane >> 2);
                float m2 = fmaxf(sMax[rl], sMax[128 + rl]);
                float mn = fmaxf(m_old[ti][hh], m2);
                corr[ti][hh] = __expf(m_old[ti][hh] - mn);
                mnew[ti][hh] = mn;
                m_old[ti][hh] = mn;
            }

        // ---- exp, P store, sums ----
        float sum_[2][2] = {{0.f, 0.f}, {0.f, 0.f}};
#pragma unroll
        for (int ti = 0; ti < 2; ++ti) {
            int r0 = wm * 32 + ti * 16 + (lane >> 2);
#pragma unroll
            for (int j = 0; j < 4; ++j) {
                float p0 = __expf(sc[ti][j][0] - mnew[ti][0]);
                float p1 = __expf(sc[ti][j][1] - mnew[ti][0]);
                float p2 = __expf(sc[ti][j][2] - mnew[ti][1]);
                float p3 = __expf(sc[ti][j][3] - mnew[ti][1]);
                sum_[ti][0] += p0 + p1;
                sum_[ti][1] += p2 + p3;
                int colc = wn * 32 + j * 8 + (lane & 3) * 2;
                uint32_t o0 = swzP(r0, colc >> 3) + (colc & 7) * 2;
                uint32_t o1 = swzP(r0 + 8, colc >> 3) + (colc & 7) * 2;
                *(uint32_t*)(smem + SM_P + o0) = pack_h2(p0, p1);
                *(uint32_t*)(smem + SM_P + o1) = pack_h2(p2, p3);
            }
        }
#pragma unroll
        for (int ti = 0; ti < 2; ++ti)
#pragma unroll
            for (int hh = 0; hh < 2; ++hh) {
                float s = sum_[ti][hh];
                s += __shfl_xor_sync(0xffffffffu, s, 1);
                s += __shfl_xor_sync(0xffffffffu, s, 2);
                if ((lane & 3) == 0) {
                    int rl = wm * 32 + ti * 16 + hh * 8 + (lane >> 2);
                    sSum[wn * 128 + rl] = s;
                }
            }
#pragma unroll
        for (int ti = 0; ti < 2; ++ti)
#pragma unroll
            for (int j = 0; j < 6; ++j) {
                acc[ti][j][0] *= corr[ti][0];
                acc[ti][j][1] *= corr[ti][0];
                acc[ti][j][2] *= corr[ti][1];
                acc[ti][j][3] *= corr[ti][1];
            }
        __syncthreads();
#pragma unroll
        for (int ti = 0; ti < 2; ++ti)
#pragma unroll
            for (int hh = 0; hh < 2; ++hh) {
                int rl = wm * 32 + ti * 16 + hh * 8 + (lane >> 2);
                l_run[ti][hh] = l_run[ti][hh] * corr[ti][hh] + sSum[rl] + sSum[128 + rl];
            }

        // ---- P.V ----
#pragma unroll
        for (int ks = 0; ks < 4; ++ks) {
            uint32_t p[2][4], v[6][2];
#pragma unroll
            for (int ti = 0; ti < 2; ++ti) {
                int r = wm * 32 + ti * 16 + (lane & 15);
                int c = ks * 2 + (lane >> 4);
                ldsm_x4(p[ti], sb + SM_P + swzP(r, c));
            }
#pragma unroll
            for (int j = 0; j < 6; ++j) {
                int rk = ks * 16 + (lane & 15);
                int c = wn * 6 + j;
                ldsm_x2t(v[j], kb + 12288 + swzQ(rk, c));
            }
#pragma unroll
            for (int ti = 0; ti < 2; ++ti)
#pragma unroll
                for (int j = 0; j < 6; ++j)
                    mma_f32(acc[ti][j], p[ti], v[j]);
        }
    }

    // ---- epilogue ----
    float inv[2][2];
#pragma unroll
    for (int ti = 0; ti < 2; ++ti)
#pragma unroll
        for (int hh = 0; hh < 2; ++hh)
            inv[ti][hh] = 1.f / l_run[ti][hh];

#pragma unroll
    for (int ti = 0; ti < 2; ++ti)
#pragma unroll
        for (int j = 0; j < 6; ++j) {
            int col = wn * 48 + j * 8 + (lane & 3) * 2;
            if (col >= HD) continue;
#pragma unroll
            for (int hh = 0; hh < 2; ++hh) {
                int s = q0 + wm * 32 + ti * 16 + hh * 8 + (lane >> 2);
                if (s >= SS) continue;
                float o0 = acc[ti][j][hh * 2] * inv[ti][hh];
                float o1 = acc[ti][j][hh * 2 + 1] * inv[ti][hh];
                size_t off = (size_t)(b * SS + s) * KK + (size_t)h * HD + col;
                *(uint32_t*)&att[off] = pack_h2(o0, o1);
            }
        }
}

// ---------------------------------------------------------------------------
extern "C" void kernel_launch(void* const* d_in, const int* in_sizes, int n_in,
                              void* d_out, int out_size)
{
    const float* hs     = (const float*)d_in[0];
    const float* w_qkv  = (const float*)d_in[1];
    const float* b_qkv  = (const float*)d_in[2];
    const float* w_proj = (const float*)d_in[3];
    const float* b_proj = (const float*)d_in[4];
    float* out = (float*)d_out;

    __half *hsp, *qkv, *att, *wq, *wp;
    cudaGetSymbolAddress((void**)&hsp, g_hs);
    cudaGetSymbolAddress((void**)&qkv, g_qkv);
    cudaGetSymbolAddress((void**)&att, g_att);
    cudaGetSymbolAddress((void**)&wq, g_wqkv);
    cudaGetSymbolAddress((void**)&wp, g_wproj);

    const int gemm_smem = STAGES * STG_BYTES;   // 48 KB
    cudaFuncSetAttribute((const void*)gemm_mma_kernel<0>,
                         cudaFuncAttributeMaxDynamicSharedMemorySize, gemm_smem);
    cudaFuncSetAttribute((const void*)gemm_mma_kernel<1>,
                         cudaFuncAttributeMaxDynamicSharedMemorySize, gemm_smem);
    cudaFuncSetAttribute((const void*)attn_tc_kernel,
                         cudaFuncAttributeMaxDynamicSharedMemorySize, SM_ATT_TOTAL);

    // 0a) round hidden_states to fp16
    {
        int n4 = MM * KK / 4;
        round_kernel<<<(n4 + 255) / 256, 256>>>((const float4*)hs, (uint2*)hsp, n4);
    }
    // 0b) transpose+round weights to fp16
    {
        dim3 g(N1 / 32, KK / 32);
        ttrunc_kernel<<<g, dim3(32, 8)>>>(w_qkv, wq, KK, N1);
    }
    {
        dim3 g(DD / 32, KK / 32);
        ttrunc_kernel<<<g, dim3(32, 8)>>>(w_proj, wp, KK, DD);
    }
    // 1) QKV projection -> single fp16 (q pre-scaled)
    {
        dim3 g(N1 / 128, (MM + 127) / 128);
        gemm_mma_kernel<1><<<g, 256, gemm_smem>>>(hsp, wq, b_qkv,
                                                  nullptr, qkv, MM, N1);
    }
    // 2) flash attention (fp16) -> plain fp16
    {
        dim3 g((SS + 127) / 128, HH, BB);
        attn_tc_kernel<<<g, 256, SM_ATT_TOTAL>>>(qkv, att);
    }
    // 3) output projection -> fp32
    {
        dim3 g(DD / 128, (MM + 127) / 128);
        gemm_mma_kernel<0><<<g, 256, gemm_smem>>>(att, wp, b_proj,
                                                  out, nullptr, MM, DD);
    }
}